// round 10
// baseline (speedup 1.0000x reference)
#include <cuda_runtime.h>
#include <cuda_bf16.h>
#include <cstdint>

#define NN 100000
#define NE 1200000
#define NB ((NN + 255) / 256)        // 391 scan blocks
#define NT128 ((NN + 127) / 128)     // 782 MMA tiles (128 rows)
#define NTILES (NN/32)               // 3125 (32-row mixgemm tiles)

// ---------------- scratch (static device memory) ---------------------------
__device__ int   g_deg[NN];
__device__ int   g_cnt[NN];
__device__ int   g_fill[NN];
__device__ int   g_rp[NN + 1];
__device__ int   g_bsum[NB + 1];
__device__ int   g_col[NE];
__device__ float g_w[NE];
__device__ float g_dinv[NN];
__device__ float g_T1[NN * 64];
__device__ float g_T2[NN * 64];
__device__ float g_T3[NN * 64];
__device__ float g_Ha[NN * 64];
__device__ float g_Hb[NN * 64];
__device__ float g_A[NN * 32];
__device__ float g_B[NN * 32];

// ---------------- setup kernels --------------------------------------------
__global__ void k_zero3() {
    int i = blockIdx.x * blockDim.x + threadIdx.x;
    if (i < NN) { g_deg[i] = 0; g_cnt[i] = 0; g_fill[i] = 0; }
}

__global__ void k_degcnt(const int* __restrict__ src, const int* __restrict__ dst) {
    int i = blockIdx.x * blockDim.x + threadIdx.x;
    if (i < NE) {
        atomicAdd(&g_deg[src[i]], 1);
        atomicAdd(&g_cnt[dst[i]], 1);
    }
}

__global__ void k_dinv() {
    int i = blockIdx.x * blockDim.x + threadIdx.x;
    if (i < NN) {
        int d = g_deg[i];
        g_dinv[i] = (d > 0) ? rsqrtf((float)d) : 0.0f;
    }
}

__global__ void k_scan1() {
    __shared__ int s[8];
    const int t = threadIdx.x;
    int i = blockIdx.x * 256 + t;
    int v = (i < NN) ? g_cnt[i] : 0;
    #pragma unroll
    for (int d = 16; d; d >>= 1) v += __shfl_down_sync(0xffffffffu, v, d);
    if ((t & 31) == 0) s[t >> 5] = v;
    __syncthreads();
    if (t < 8) {
        int x = s[t];
        #pragma unroll
        for (int d = 4; d; d >>= 1) x += __shfl_down_sync(0xffu, x, d);
        if (t == 0) g_bsum[blockIdx.x] = x;
    }
}

__global__ void k_scan2() {
    __shared__ int wsum[16];
    const int t = threadIdx.x;
    int v = (t < NB) ? g_bsum[t] : 0;
    int xv = v;
    #pragma unroll
    for (int d = 1; d < 32; d <<= 1) {
        int y = __shfl_up_sync(0xffffffffu, xv, d);
        if ((t & 31) >= d) xv += y;
    }
    if ((t & 31) == 31) wsum[t >> 5] = xv;
    __syncthreads();
    if (t < 16) {
        int wv = wsum[t];
        int yv = wv;
        #pragma unroll
        for (int d = 1; d < 16; d <<= 1) {
            int z = __shfl_up_sync(0xffffu, yv, d);
            if (t >= d) yv += z;
        }
        wsum[t] = yv - wv;
    }
    __syncthreads();
    int incl = xv + wsum[t >> 5];
    int excl = incl - v;
    if (t < NB) g_bsum[t] = excl;
    if (t == NB - 1) g_rp[NN] = incl;
}

__global__ void k_scan3() {
    __shared__ int wsum[8];
    const int t = threadIdx.x;
    int i = blockIdx.x * 256 + t;
    int v = (i < NN) ? g_cnt[i] : 0;
    int xv = v;
    #pragma unroll
    for (int d = 1; d < 32; d <<= 1) {
        int y = __shfl_up_sync(0xffffffffu, xv, d);
        if ((t & 31) >= d) xv += y;
    }
    if ((t & 31) == 31) wsum[t >> 5] = xv;
    __syncthreads();
    if (t < 8) {
        int wv = wsum[t];
        int yv = wv;
        #pragma unroll
        for (int d = 1; d < 8; d <<= 1) {
            int z = __shfl_up_sync(0xffu, yv, d);
            if (t >= d) yv += z;
        }
        wsum[t] = yv - wv;
    }
    __syncthreads();
    if (i < NN) g_rp[i] = xv - v + wsum[t >> 5] + g_bsum[blockIdx.x];
}

__global__ void k_scatter(const int* __restrict__ src, const int* __restrict__ dst) {
    int i = blockIdx.x * blockDim.x + threadIdx.x;
    if (i < NE) {
        int s = src[i], d = dst[i];
        int pos = g_rp[d] + atomicAdd(&g_fill[d], 1);
        g_col[pos] = s;
        g_w[pos] = -g_dinv[s] * g_dinv[d];
    }
}

// ---------------- sparse matvec: out = alpha * (L z) + beta * sub ----------
__global__ void k_lmv64(const float* __restrict__ z, const float* __restrict__ sub,
                        float* __restrict__ outp, float alpha, float beta) {
    int gt = blockIdx.x * blockDim.x + threadIdx.x;
    int node = gt >> 5;
    if (node >= NN) return;
    int lane = gt & 31;
    int beg = g_rp[node], end = g_rp[node + 1];
    const float2* z2 = (const float2*)z;
    float2 acc = make_float2(0.f, 0.f);
    for (int e = beg; e < end; e++) {
        int s = g_col[e];
        float we = g_w[e];
        float2 v = z2[s * 32 + lane];
        acc.x += we * v.x;
        acc.y += we * v.y;
    }
    float2 r;
    if (sub) {
        float2 sv = ((const float2*)sub)[node * 32 + lane];
        r.x = alpha * acc.x + beta * sv.x;
        r.y = alpha * acc.y + beta * sv.y;
    } else {
        r.x = alpha * acc.x;
        r.y = alpha * acc.y;
    }
    ((float2*)outp)[node * 32 + lane] = r;
}

// ============== mma.sync (HMMA) bf16-split layer GEMM ======================
// out = relu([T0|T1|T2|T3]@Wk + bk) + T0@Ws + bs, tile 128 rows x 64 cols
// bf16 split: D = Ah*Bh + Al*Bh + Ah*Bl  (fp32 accumulate)
// smem word offsets (u32 units); A/B stored as bf16-pairs (2 k per u32)
#define AW_HI 0
#define AW_LO 16896
#define BK_HI 33792
#define BK_LO 42240
#define BS_HI 50688
#define BS_LO 52992
#define BIAS_K 55296
#define BIAS_S 55360
#define SMEM_MMA (55424 * 4)   // 221,696 B

__device__ __forceinline__ void bf16_split(float x, unsigned short& h, unsigned short& l) {
    __nv_bfloat16 hb = __float2bfloat16(x);
    __nv_bfloat16 lb = __float2bfloat16(x - __bfloat162float(hb));
    h = *(unsigned short*)&hb;
    l = *(unsigned short*)&lb;
}
__device__ __forceinline__ void pack2(float a, float b, uint32_t& hi, uint32_t& lo) {
    unsigned short h0, l0, h1, l1;
    bf16_split(a, h0, l0); bf16_split(b, h1, l1);
    hi = (uint32_t)h0 | ((uint32_t)h1 << 16);
    lo = (uint32_t)l0 | ((uint32_t)l1 << 16);
}
__device__ __forceinline__ void mma_bf16(float4& d,
        uint32_t a0, uint32_t a1, uint32_t a2, uint32_t a3,
        uint32_t b0, uint32_t b1) {
    asm volatile(
        "mma.sync.aligned.m16n8k16.row.col.f32.bf16.bf16.f32 "
        "{%0,%1,%2,%3}, {%4,%5,%6,%7}, {%8,%9}, {%0,%1,%2,%3};\n"
        : "+f"(d.x), "+f"(d.y), "+f"(d.z), "+f"(d.w)
        : "r"(a0), "r"(a1), "r"(a2), "r"(a3), "r"(b0), "r"(b1));
}

__global__ void __launch_bounds__(256, 1) k_layer_mma(
        const float* __restrict__ T0,
        const float* __restrict__ Wk, const float* __restrict__ bk,
        const float* __restrict__ Ws, const float* __restrict__ bs,
        float* __restrict__ outp) {
    extern __shared__ uint32_t smw[];
    float* bk_s = (float*)(smw + BIAS_K);
    float* bs_s = (float*)(smw + BIAS_S);
    const int t = threadIdx.x;            // 256 threads, 8 warps
    const int wid = t >> 5, lid = t & 31;
    const int g = lid >> 2, tg = lid & 3;

    // ---- stage Wk^T hi/lo: B[n][kpair], stride 132 (once per block) ----
    for (int i = t; i < 64 * 128; i += 256) {
        int n = i >> 7, kp = i & 127;
        uint32_t hi, lo;
        pack2(Wk[(2 * kp) * 64 + n], Wk[(2 * kp + 1) * 64 + n], hi, lo);
        smw[BK_HI + n * 132 + kp] = hi;
        smw[BK_LO + n * 132 + kp] = lo;
    }
    // ---- stage Ws^T hi/lo: [n][kpair 0..31], stride 36 ----
    for (int i = t; i < 64 * 32; i += 256) {
        int n = i >> 5, kp = i & 31;
        uint32_t hi, lo;
        pack2(Ws[(2 * kp) * 64 + n], Ws[(2 * kp + 1) * 64 + n], hi, lo);
        smw[BS_HI + n * 36 + kp] = hi;
        smw[BS_LO + n * 36 + kp] = lo;
    }
    if (t < 64) { bk_s[t] = bk[t]; bs_s[t] = bs[t]; }

    const float2* s0 = (const float2*)T0;
    const float2* s1 = (const float2*)g_T1;
    const float2* s2 = (const float2*)g_T2;
    const float2* s3 = (const float2*)g_T3;

    for (int tile = blockIdx.x; tile < NT128; tile += gridDim.x) {
        const int rowbase = tile * 128;
        __syncthreads();   // prior tile's compute done before restaging A

        // ---- stage A hi/lo: [row][kpair], stride 132 ----
        for (int i = t; i < 128 * 128; i += 256) {
            int r = i >> 7, kp = i & 127;
            int seg = kp >> 5, idx = kp & 31;
            int row = min(rowbase + r, NN - 1);
            const float2* sp = (seg == 0) ? s0 : (seg == 1) ? s1 : (seg == 2) ? s2 : s3;
            float2 v = sp[row * 32 + idx];
            uint32_t hi, lo;
            pack2(v.x, v.y, hi, lo);
            smw[AW_HI + r * 132 + kp] = hi;
            smw[AW_LO + r * 132 + kp] = lo;
        }
        __syncthreads();

        // ---- compute: warp owns rows rowbase + wid*16 .. +15 ----
        float4 accK[8], accS[8];
        #pragma unroll
        for (int n = 0; n < 8; n++) {
            accK[n] = make_float4(0.f, 0.f, 0.f, 0.f);
            accS[n] = make_float4(0.f, 0.f, 0.f, 0.f);
        }
        const int ar0 = (wid * 16 + g) * 132;
        const int ar1 = ar0 + 8 * 132;

        #pragma unroll 4
        for (int kb = 0; kb < 16; kb++) {
            const int ka = kb * 8 + tg;
            uint32_t a0h = smw[AW_HI + ar0 + ka];
            uint32_t a1h = smw[AW_HI + ar1 + ka];
            uint32_t a2h = smw[AW_HI + ar0 + ka + 4];
            uint32_t a3h = smw[AW_HI + ar1 + ka + 4];
            uint32_t a0l = smw[AW_LO + ar0 + ka];
            uint32_t a1l = smw[AW_LO + ar1 + ka];
            uint32_t a2l = smw[AW_LO + ar0 + ka + 4];
            uint32_t a3l = smw[AW_LO + ar1 + ka + 4];
            #pragma unroll
            for (int n = 0; n < 8; n++) {
                const int bi = (n * 8 + g) * 132 + ka;
                uint32_t b0h = smw[BK_HI + bi];
                uint32_t b1h = smw[BK_HI + bi + 4];
                uint32_t b0l = smw[BK_LO + bi];
                uint32_t b1l = smw[BK_LO + bi + 4];
                mma_bf16(accK[n], a0h, a1h, a2h, a3h, b0h, b1h);
                mma_bf16(accK[n], a0l, a1l, a2l, a3l, b0h, b1h);
                mma_bf16(accK[n], a0h, a1h, a2h, a3h, b0l, b1l);
            }
            if (kb < 4) {   // skip GEMM over K=64 (T0 columns)
                const int ks = kb * 8 + tg;
                #pragma unroll
                for (int n = 0; n < 8; n++) {
                    const int bi = (n * 8 + g) * 36 + ks;
                    uint32_t b0h = smw[BS_HI + bi];
                    uint32_t b1h = smw[BS_HI + bi + 4];
                    uint32_t b0l = smw[BS_LO + bi];
                    uint32_t b1l = smw[BS_LO + bi + 4];
                    mma_bf16(accS[n], a0h, a1h, a2h, a3h, b0h, b1h);
                    mma_bf16(accS[n], a0l, a1l, a2l, a3l, b0h, b1h);
                    mma_bf16(accS[n], a0h, a1h, a2h, a3h, b0l, b1l);
                }
            }
        }

        // ---- epilogue ----
        const int row0 = rowbase + wid * 16 + g;
        const int row1 = row0 + 8;
        #pragma unroll
        for (int n = 0; n < 8; n++) {
            const int col = n * 8 + 2 * tg;
            float bk0 = bk_s[col], bk1 = bk_s[col + 1];
            float bs0 = bs_s[col], bs1 = bs_s[col + 1];
            if (row0 < NN) {
                float2 o;
                o.x = fmaxf(accK[n].x + bk0, 0.f) + accS[n].x + bs0;
                o.y = fmaxf(accK[n].y + bk1, 0.f) + accS[n].y + bs1;
                *(float2*)&outp[row0 * 64 + col] = o;
            }
            if (row1 < NN) {
                float2 o;
                o.x = fmaxf(accK[n].z + bk0, 0.f) + accS[n].z + bs0;
                o.y = fmaxf(accK[n].w + bk1, 0.f) + accS[n].w + bs1;
                *(float2*)&outp[row1 * 64 + col] = o;
            }
        }
    }
}

// ---------------- mix head GEMM: A = hc@W1, B = hc@W0 + b ------------------
#define SMEM_MIX (12320 * 4)
__global__ void __launch_bounds__(256, 4) k_mixgemm(
        const float* __restrict__ H, const float* __restrict__ x,
        const float* __restrict__ mw, const float* __restrict__ mb) {
    extern __shared__ float sm[];
    float* Wm_s = sm;           // 8192  [128][64]: cols 0..31 = W1, 32..63 = W0
    float* ins  = sm + 8192;    // 4096  [32 rows][128]
    float* mb_s = sm + 12288;   // 32
    const int t = threadIdx.x;

    for (int j = t; j < 8192; j += 256) {
        int f = j >> 6, col = j & 63;
        Wm_s[j] = (col < 32) ? mw[128 * 32 + f * 32 + col] : mw[f * 32 + (col - 32)];
    }
    if (t < 32) mb_s[t] = mb[t];

    const int cg = (t & 15) * 4;
    const int r0 = (t >> 4) * 2;

    for (int tile = blockIdx.x; tile < NTILES; tile += gridDim.x) {
        const int rowbase = tile * 32;
        __syncthreads();
        {
            const float4* sH = (const float4*)H;
            const float4* sx = (const float4*)x;
            #pragma unroll
            for (int j = 0; j < 2; j++) {
                int i = t + j * 256;
                int r = i >> 4, f4 = i & 15;
                int gidx = (rowbase + r) * 16 + f4;
                *(float4*)&ins[r * 128 +      f4 * 4] = sH[gidx];
                *(float4*)&ins[r * 128 + 64 + f4 * 4] = sx[gidx];
            }
        }
        __syncthreads();

        const float* in0 = &ins[r0 * 128];
        const float* in1 = in0 + 128;
        float4 acc0 = make_float4(0, 0, 0, 0), acc1 = acc0;
        #pragma unroll 8
        for (int kk = 0; kk < 128; kk++) {
            float4 wv = *(const float4*)&Wm_s[kk * 64 + cg];
            float a0 = in0[kk], a1 = in1[kk];
            acc0.x += a0 * wv.x; acc0.y += a0 * wv.y; acc0.z += a0 * wv.z; acc0.w += a0 * wv.w;
            acc1.x += a1 * wv.x; acc1.y += a1 * wv.y; acc1.z += a1 * wv.z; acc1.w += a1 * wv.w;
        }
        if (cg < 32) {
            *(float4*)&g_A[(rowbase + r0) * 32 + cg]     = acc0;
            *(float4*)&g_A[(rowbase + r0 + 1) * 32 + cg] = acc1;
        } else {
            float4 bv = *(const float4*)&mb_s[cg - 32];
            acc0.x += bv.x; acc0.y += bv.y; acc0.z += bv.z; acc0.w += bv.w;
            acc1.x += bv.x; acc1.y += bv.y; acc1.z += bv.z; acc1.w += bv.w;
            *(float4*)&g_B[(rowbase + r0) * 32 + cg - 32]     = acc0;
            *(float4*)&g_B[(rowbase + r0 + 1) * 32 + cg - 32] = acc1;
        }
    }
}

// ---------------- final: out = B + L(A) (width 32) -------------------------
__global__ void k_mixlmv(float* __restrict__ outp) {
    int gt = blockIdx.x * blockDim.x + threadIdx.x;
    int node = gt >> 5;
    if (node >= NN) return;
    int lane = gt & 31;
    int beg = g_rp[node], end = g_rp[node + 1];
    float acc = 0.f;
    for (int e = beg; e < end; e++) {
        acc += g_w[e] * g_A[g_col[e] * 32 + lane];
    }
    outp[node * 32 + lane] = g_B[node * 32 + lane] + acc;
}

// ---------------- launch ---------------------------------------------------
extern "C" void kernel_launch(void* const* d_in, const int* in_sizes, int n_in,
                              void* d_out, int out_size) {
    const float* x  = (const float*)d_in[0];
    const int*   ei = (const int*)d_in[1];
    const float* kw = (const float*)d_in[2];   // [3][4][64][64]
    const float* kb = (const float*)d_in[3];   // [3][64]
    const float* sw = (const float*)d_in[4];   // [3][64][64]
    const float* sb = (const float*)d_in[5];   // [3][64]
    const float* mw = (const float*)d_in[6];   // [2][128][32]
    const float* mb = (const float*)d_in[7];   // [32]
    float* outp = (float*)d_out;
    const int* src = ei;
    const int* dst = ei + NE;

    float *T1, *T2, *T3, *Ha, *Hb;
    cudaGetSymbolAddress((void**)&T1, g_T1);
    cudaGetSymbolAddress((void**)&T2, g_T2);
    cudaGetSymbolAddress((void**)&T3, g_T3);
    cudaGetSymbolAddress((void**)&Ha, g_Ha);
    cudaGetSymbolAddress((void**)&Hb, g_Hb);

    cudaFuncSetAttribute(k_layer_mma, cudaFuncAttributeMaxDynamicSharedMemorySize, SMEM_MMA);
    cudaFuncSetAttribute(k_mixgemm, cudaFuncAttributeMaxDynamicSharedMemorySize, SMEM_MIX);

    const int gE = (NE + 255) / 256;       // 4688
    const int gN = NB;                     // 391
    const int gW = (NN * 32 + 255) / 256;  // 12500 (warp per node)
    const int gG = 148;                    // MMA layer: persistent, 1 block/SM
    const int gM = 592;                    // mixgemm grid

    // graph setup: degrees, dinv, CSR by dst
    k_zero3<<<gN, 256>>>();
    k_degcnt<<<gE, 256>>>(src, dst);
    k_dinv<<<gN, 256>>>();
    k_scan1<<<gN, 256>>>();
    k_scan2<<<1, 512>>>();
    k_scan3<<<gN, 256>>>();
    k_scatter<<<gE, 256>>>(src, dst);

    // layer 0: input = x, output = Hb
    k_lmv64<<<gW, 256>>>(x, nullptr, T1, 1.f, 0.f);
    k_lmv64<<<gW, 256>>>(T1, x, T2, 2.f, -1.f);
    k_lmv64<<<gW, 256>>>(T2, T1, T3, 2.f, -1.f);
    k_layer_mma<<<gG, 256, SMEM_MMA>>>(x, kw, kb, sw, sb, Hb);

    // layer 1: Hb -> Ha
    k_lmv64<<<gW, 256>>>(Hb, nullptr, T1, 1.f, 0.f);
    k_lmv64<<<gW, 256>>>(T1, Hb, T2, 2.f, -1.f);
    k_lmv64<<<gW, 256>>>(T2, T1, T3, 2.f, -1.f);
    k_layer_mma<<<gG, 256, SMEM_MMA>>>(Hb, kw + 4 * 64 * 64, kb + 64, sw + 64 * 64, sb + 64, Ha);

    // layer 2: Ha -> Hb
    k_lmv64<<<gW, 256>>>(Ha, nullptr, T1, 1.f, 0.f);
    k_lmv64<<<gW, 256>>>(T1, Ha, T2, 2.f, -1.f);
    k_lmv64<<<gW, 256>>>(T2, T1, T3, 2.f, -1.f);
    k_layer_mma<<<gG, 256, SMEM_MMA>>>(Ha, kw + 8 * 64 * 64, kb + 128, sw + 2 * 64 * 64, sb + 128, Hb);

    // mix head: A = [Hb|x]@W1, B = [Hb|x]@W0 + b; out = B + L(A)
    k_mixgemm<<<gM, 256, SMEM_MIX>>>(Hb, x, mw, mb);
    k_mixlmv<<<gW, 256>>>(outp);
}

// round 11
// speedup vs baseline: 1.2175x; 1.2175x over previous
#include <cuda_runtime.h>
#include <cuda_fp16.h>
#include <cstdint>

#define NN 100000
#define NE 1200000
#define NB ((NN + 255) / 256)        // 391 scan blocks
#define NTILES (NN/32)               // 3125 (32-row GEMM tiles)

// ---------------- scratch (static device memory) ---------------------------
__device__ int     g_deg[NN];
__device__ int     g_cnt[NN];
__device__ int     g_fill[NN];
__device__ int     g_rp[NN + 1];
__device__ int     g_bsum[NB + 1];
__device__ int     g_col[NE];
__device__ float   g_w[NE];
__device__ float   g_dinv[NN];
__device__ float   g_T1[NN * 64];
__device__ float   g_T2[NN * 64];
__device__ float   g_T3[NN * 64];
__device__ float   g_Ha[NN * 64];
__device__ float   g_Hb[NN * 64];
__device__ float   g_A[NN * 32];
__device__ float   g_B[NN * 32];
__device__ __half2 g_X16[NN * 32];   // fp16 copy of layer input (x or H)
__device__ __half2 g_T1h[NN * 32];
__device__ __half2 g_T2h[NN * 32];

// ---------------- setup kernels --------------------------------------------
__global__ void k_zero3() {
    int i = blockIdx.x * blockDim.x + threadIdx.x;
    if (i < NN) { g_deg[i] = 0; g_cnt[i] = 0; g_fill[i] = 0; }
}

__global__ void k_degcnt(const int* __restrict__ src, const int* __restrict__ dst) {
    int i = blockIdx.x * blockDim.x + threadIdx.x;
    if (i < NE) {
        atomicAdd(&g_deg[src[i]], 1);
        atomicAdd(&g_cnt[dst[i]], 1);
    }
}

__global__ void k_dinv() {
    int i = blockIdx.x * blockDim.x + threadIdx.x;
    if (i < NN) {
        int d = g_deg[i];
        g_dinv[i] = (d > 0) ? rsqrtf((float)d) : 0.0f;
    }
}

__global__ void k_tohalf(const float* __restrict__ z) {
    int i = blockIdx.x * blockDim.x + threadIdx.x;
    if (i < NN * 32) {
        float2 v = ((const float2*)z)[i];
        g_X16[i] = __floats2half2_rn(v.x, v.y);
    }
}

__global__ void k_scan1() {
    __shared__ int s[8];
    const int t = threadIdx.x;
    int i = blockIdx.x * 256 + t;
    int v = (i < NN) ? g_cnt[i] : 0;
    #pragma unroll
    for (int d = 16; d; d >>= 1) v += __shfl_down_sync(0xffffffffu, v, d);
    if ((t & 31) == 0) s[t >> 5] = v;
    __syncthreads();
    if (t < 8) {
        int x = s[t];
        #pragma unroll
        for (int d = 4; d; d >>= 1) x += __shfl_down_sync(0xffu, x, d);
        if (t == 0) g_bsum[blockIdx.x] = x;
    }
}

__global__ void k_scan2() {
    __shared__ int wsum[16];
    const int t = threadIdx.x;
    int v = (t < NB) ? g_bsum[t] : 0;
    int xv = v;
    #pragma unroll
    for (int d = 1; d < 32; d <<= 1) {
        int y = __shfl_up_sync(0xffffffffu, xv, d);
        if ((t & 31) >= d) xv += y;
    }
    if ((t & 31) == 31) wsum[t >> 5] = xv;
    __syncthreads();
    if (t < 16) {
        int wv = wsum[t];
        int yv = wv;
        #pragma unroll
        for (int d = 1; d < 16; d <<= 1) {
            int z = __shfl_up_sync(0xffffu, yv, d);
            if (t >= d) yv += z;
        }
        wsum[t] = yv - wv;
    }
    __syncthreads();
    int incl = xv + wsum[t >> 5];
    int excl = incl - v;
    if (t < NB) g_bsum[t] = excl;
    if (t == NB - 1) g_rp[NN] = incl;
}

__global__ void k_scan3() {
    __shared__ int wsum[8];
    const int t = threadIdx.x;
    int i = blockIdx.x * 256 + t;
    int v = (i < NN) ? g_cnt[i] : 0;
    int xv = v;
    #pragma unroll
    for (int d = 1; d < 32; d <<= 1) {
        int y = __shfl_up_sync(0xffffffffu, xv, d);
        if ((t & 31) >= d) xv += y;
    }
    if ((t & 31) == 31) wsum[t >> 5] = xv;
    __syncthreads();
    if (t < 8) {
        int wv = wsum[t];
        int yv = wv;
        #pragma unroll
        for (int d = 1; d < 8; d <<= 1) {
            int z = __shfl_up_sync(0xffu, yv, d);
            if (t >= d) yv += z;
        }
        wsum[t] = yv - wv;
    }
    __syncthreads();
    if (i < NN) g_rp[i] = xv - v + wsum[t >> 5] + g_bsum[blockIdx.x];
}

__global__ void k_scatter(const int* __restrict__ src, const int* __restrict__ dst) {
    int i = blockIdx.x * blockDim.x + threadIdx.x;
    if (i < NE) {
        int s = src[i], d = dst[i];
        int pos = g_rp[d] + atomicAdd(&g_fill[d], 1);
        g_col[pos] = s;
        g_w[pos] = -g_dinv[s] * g_dinv[d];
    }
}

// ------ sparse matvec, fp16 gather: out = alpha*(L zh) + beta*sub ----------
// outp fp32 always; outh fp16 copy if non-null
__global__ void k_lmv64h(const __half2* __restrict__ zh, const float* __restrict__ sub,
                         float* __restrict__ outp, __half2* __restrict__ outh,
                         float alpha, float beta) {
    int gt = blockIdx.x * blockDim.x + threadIdx.x;
    int node = gt >> 5;
    if (node >= NN) return;
    int lane = gt & 31;
    int beg = g_rp[node], end = g_rp[node + 1];
    float2 acc = make_float2(0.f, 0.f);
    for (int e = beg; e < end; e++) {
        int s = g_col[e];
        float we = g_w[e];
        float2 v = __half22float2(zh[s * 32 + lane]);
        acc.x += we * v.x;
        acc.y += we * v.y;
    }
    float2 r;
    if (sub) {
        float2 sv = ((const float2*)sub)[node * 32 + lane];
        r.x = alpha * acc.x + beta * sv.x;
        r.y = alpha * acc.y + beta * sv.y;
    } else {
        r.x = alpha * acc.x;
        r.y = alpha * acc.y;
    }
    ((float2*)outp)[node * 32 + lane] = r;
    if (outh) outh[node * 32 + lane] = __floats2half2_rn(r.x, r.y);
}

// ---------------- fused layer GEMM -----------------------------------------
// out = relu([T0|T1|T2|T3] @ Wk + bk) + T0 @ Ws + bs   (+ fp16 copy of out)
#define SMEM_LAYER (28928 * 4)
__global__ void __launch_bounds__(256, 2) k_layer(
        const float* __restrict__ T0,
        const float* __restrict__ Wk, const float* __restrict__ bk,
        const float* __restrict__ Ws, const float* __restrict__ bs,
        float* __restrict__ outp, __half2* __restrict__ outh) {
    extern __shared__ float sm[];
    float* Wk_s = sm;            // 16384
    float* Ws_s = sm + 16384;    // 4096
    float* ins  = sm + 20480;    // 8192  [32 rows][256]
    float* bk_s = sm + 28672;    // 64
    float* bs_s = sm + 28736;    // 64
    const int t = threadIdx.x;   // 256 threads

    for (int j = t; j < 4096; j += 256) ((float4*)Wk_s)[j] = ((const float4*)Wk)[j];
    for (int j = t; j < 1024; j += 256) ((float4*)Ws_s)[j] = ((const float4*)Ws)[j];
    if (t < 64) { bk_s[t] = bk[t]; bs_s[t] = bs[t]; }

    const int cg = (t & 15) * 4;   // output col base (4 cols)
    const int r0 = (t >> 4) * 2;   // row base (2 rows)

    for (int tile = blockIdx.x; tile < NTILES; tile += gridDim.x) {
        const int rowbase = tile * 32;
        __syncthreads();
        {
            const float4* s0 = (const float4*)T0;
            const float4* s1 = (const float4*)g_T1;
            const float4* s2 = (const float4*)g_T2;
            const float4* s3 = (const float4*)g_T3;
            #pragma unroll
            for (int j = 0; j < 2; j++) {
                int i = t + j * 256;
                int r = i >> 4, f4 = i & 15;
                int gidx = (rowbase + r) * 16 + f4;
                *(float4*)&ins[r * 256 +   0 + f4 * 4] = s0[gidx];
                *(float4*)&ins[r * 256 +  64 + f4 * 4] = s1[gidx];
                *(float4*)&ins[r * 256 + 128 + f4 * 4] = s2[gidx];
                *(float4*)&ins[r * 256 + 192 + f4 * 4] = s3[gidx];
            }
        }
        __syncthreads();

        const float* in0 = &ins[r0 * 256];
        const float* in1 = in0 + 256;
        float4 acc0 = make_float4(0, 0, 0, 0), acc1 = acc0;
        #pragma unroll 8
        for (int kk = 0; kk < 256; kk++) {
            float4 wv = *(const float4*)&Wk_s[kk * 64 + cg];
            float a0 = in0[kk], a1 = in1[kk];
            acc0.x += a0 * wv.x; acc0.y += a0 * wv.y; acc0.z += a0 * wv.z; acc0.w += a0 * wv.w;
            acc1.x += a1 * wv.x; acc1.y += a1 * wv.y; acc1.z += a1 * wv.z; acc1.w += a1 * wv.w;
        }
        float4 sk0 = make_float4(0, 0, 0, 0), sk1 = sk0;
        #pragma unroll 8
        for (int kk = 0; kk < 64; kk++) {
            float4 wv = *(const float4*)&Ws_s[kk * 64 + cg];
            float a0 = in0[kk], a1 = in1[kk];
            sk0.x += a0 * wv.x; sk0.y += a0 * wv.y; sk0.z += a0 * wv.z; sk0.w += a0 * wv.w;
            sk1.x += a1 * wv.x; sk1.y += a1 * wv.y; sk1.z += a1 * wv.z; sk1.w += a1 * wv.w;
        }
        float4 bkv = *(const float4*)&bk_s[cg];
        float4 bsv = *(const float4*)&bs_s[cg];
        float4 o0, o1;
        o0.x = fmaxf(acc0.x + bkv.x, 0.f) + sk0.x + bsv.x;
        o0.y = fmaxf(acc0.y + bkv.y, 0.f) + sk0.y + bsv.y;
        o0.z = fmaxf(acc0.z + bkv.z, 0.f) + sk0.z + bsv.z;
        o0.w = fmaxf(acc0.w + bkv.w, 0.f) + sk0.w + bsv.w;
        o1.x = fmaxf(acc1.x + bkv.x, 0.f) + sk1.x + bsv.x;
        o1.y = fmaxf(acc1.y + bkv.y, 0.f) + sk1.y + bsv.y;
        o1.z = fmaxf(acc1.z + bkv.z, 0.f) + sk1.z + bsv.z;
        o1.w = fmaxf(acc1.w + bkv.w, 0.f) + sk1.w + bsv.w;
        const int ro0 = rowbase + r0, ro1 = ro0 + 1;
        *(float4*)&outp[ro0 * 64 + cg] = o0;
        *(float4*)&outp[ro1 * 64 + cg] = o1;
        outh[(ro0 * 64 + cg) / 2]     = __floats2half2_rn(o0.x, o0.y);
        outh[(ro0 * 64 + cg) / 2 + 1] = __floats2half2_rn(o0.z, o0.w);
        outh[(ro1 * 64 + cg) / 2]     = __floats2half2_rn(o1.x, o1.y);
        outh[(ro1 * 64 + cg) / 2 + 1] = __floats2half2_rn(o1.z, o1.w);
    }
}

// ---------------- mix head GEMM: A = hc@W1, B = hc@W0 + b ------------------
#define SMEM_MIX (12320 * 4)
__global__ void __launch_bounds__(256, 4) k_mixgemm(
        const float* __restrict__ H, const float* __restrict__ x,
        const float* __restrict__ mw, const float* __restrict__ mb) {
    extern __shared__ float sm[];
    float* Wm_s = sm;           // 8192  [128][64]: cols 0..31 = W1, 32..63 = W0
    float* ins  = sm + 8192;    // 4096  [32 rows][128]
    float* mb_s = sm + 12288;   // 32
    const int t = threadIdx.x;

    for (int j = t; j < 8192; j += 256) {
        int f = j >> 6, col = j & 63;
        Wm_s[j] = (col < 32) ? mw[128 * 32 + f * 32 + col] : mw[f * 32 + (col - 32)];
    }
    if (t < 32) mb_s[t] = mb[t];

    const int cg = (t & 15) * 4;
    const int r0 = (t >> 4) * 2;

    for (int tile = blockIdx.x; tile < NTILES; tile += gridDim.x) {
        const int rowbase = tile * 32;
        __syncthreads();
        {
            const float4* sH = (const float4*)H;
            const float4* sx = (const float4*)x;
            #pragma unroll
            for (int j = 0; j < 2; j++) {
                int i = t + j * 256;
                int r = i >> 4, f4 = i & 15;
                int gidx = (rowbase + r) * 16 + f4;
                *(float4*)&ins[r * 128 +      f4 * 4] = sH[gidx];
                *(float4*)&ins[r * 128 + 64 + f4 * 4] = sx[gidx];
            }
        }
        __syncthreads();

        const float* in0 = &ins[r0 * 128];
        const float* in1 = in0 + 128;
        float4 acc0 = make_float4(0, 0, 0, 0), acc1 = acc0;
        #pragma unroll 8
        for (int kk = 0; kk < 128; kk++) {
            float4 wv = *(const float4*)&Wm_s[kk * 64 + cg];
            float a0 = in0[kk], a1 = in1[kk];
            acc0.x += a0 * wv.x; acc0.y += a0 * wv.y; acc0.z += a0 * wv.z; acc0.w += a0 * wv.w;
            acc1.x += a1 * wv.x; acc1.y += a1 * wv.y; acc1.z += a1 * wv.z; acc1.w += a1 * wv.w;
        }
        if (cg < 32) {
            *(float4*)&g_A[(rowbase + r0) * 32 + cg]     = acc0;
            *(float4*)&g_A[(rowbase + r0 + 1) * 32 + cg] = acc1;
        } else {
            float4 bv = *(const float4*)&mb_s[cg - 32];
            acc0.x += bv.x; acc0.y += bv.y; acc0.z += bv.z; acc0.w += bv.w;
            acc1.x += bv.x; acc1.y += bv.y; acc1.z += bv.z; acc1.w += bv.w;
            *(float4*)&g_B[(rowbase + r0) * 32 + cg - 32]     = acc0;
            *(float4*)&g_B[(rowbase + r0 + 1) * 32 + cg - 32] = acc1;
        }
    }
}

// ---------------- final: out = B + L(A) (width 32, fp32) -------------------
__global__ void k_mixlmv(float* __restrict__ outp) {
    int gt = blockIdx.x * blockDim.x + threadIdx.x;
    int node = gt >> 5;
    if (node >= NN) return;
    int lane = gt & 31;
    int beg = g_rp[node], end = g_rp[node + 1];
    float acc = 0.f;
    for (int e = beg; e < end; e++) {
        acc += g_w[e] * g_A[g_col[e] * 32 + lane];
    }
    outp[node * 32 + lane] = g_B[node * 32 + lane] + acc;
}

// ---------------- launch ---------------------------------------------------
extern "C" void kernel_launch(void* const* d_in, const int* in_sizes, int n_in,
                              void* d_out, int out_size) {
    const float* x  = (const float*)d_in[0];
    const int*   ei = (const int*)d_in[1];
    const float* kw = (const float*)d_in[2];   // [3][4][64][64]
    const float* kb = (const float*)d_in[3];   // [3][64]
    const float* sw = (const float*)d_in[4];   // [3][64][64]
    const float* sb = (const float*)d_in[5];   // [3][64]
    const float* mw = (const float*)d_in[6];   // [2][128][32]
    const float* mb = (const float*)d_in[7];   // [32]
    float* outp = (float*)d_out;
    const int* src = ei;
    const int* dst = ei + NE;

    float *T1, *T2, *T3, *Ha, *Hb;
    __half2 *X16, *T1h, *T2h;
    cudaGetSymbolAddress((void**)&T1, g_T1);
    cudaGetSymbolAddress((void**)&T2, g_T2);
    cudaGetSymbolAddress((void**)&T3, g_T3);
    cudaGetSymbolAddress((void**)&Ha, g_Ha);
    cudaGetSymbolAddress((void**)&Hb, g_Hb);
    cudaGetSymbolAddress((void**)&X16, g_X16);
    cudaGetSymbolAddress((void**)&T1h, g_T1h);
    cudaGetSymbolAddress((void**)&T2h, g_T2h);

    cudaFuncSetAttribute(k_layer, cudaFuncAttributeMaxDynamicSharedMemorySize, SMEM_LAYER);
    cudaFuncSetAttribute(k_mixgemm, cudaFuncAttributeMaxDynamicSharedMemorySize, SMEM_MIX);

    const int gE = (NE + 255) / 256;       // 4688
    const int gN = NB;                     // 391
    const int gH = (NN * 32 + 255) / 256;  // 12500 (also element grid for tohalf)
    const int gW = (NN * 32 + 255) / 256;  // 12500 (warp per node)
    const int gG = 296;                    // k_layer: 2 blocks/SM target
    const int gM = 592;                    // mixgemm grid

    // graph setup: degrees, dinv, CSR by dst; fp16 copy of x
    k_zero3<<<gN, 256>>>();
    k_degcnt<<<gE, 256>>>(src, dst);
    k_dinv<<<gN, 256>>>();
    k_scan1<<<gN, 256>>>();
    k_scan2<<<1, 512>>>();
    k_scan3<<<gN, 256>>>();
    k_scatter<<<gE, 256>>>(src, dst);
    k_tohalf<<<gH, 256>>>(x);

    // layer 0: input = x (fp16 gather copy in X16), output = Hb (+X16)
    k_lmv64h<<<gW, 256>>>(X16, nullptr, T1, T1h, 1.f, 0.f);
    k_lmv64h<<<gW, 256>>>(T1h, x, T2, T2h, 2.f, -1.f);
    k_lmv64h<<<gW, 256>>>(T2h, T1, T3, nullptr, 2.f, -1.f);
    k_layer<<<gG, 256, SMEM_LAYER>>>(x, kw, kb, sw, sb, Hb, X16);

    // layer 1: Hb -> Ha (fp16 copy of Hb is in X16)
    k_lmv64h<<<gW, 256>>>(X16, nullptr, T1, T1h, 1.f, 0.f);
    k_lmv64h<<<gW, 256>>>(T1h, Hb, T2, T2h, 2.f, -1.f);
    k_lmv64h<<<gW, 256>>>(T2h, T1, T3, nullptr, 2.f, -1.f);
    k_layer<<<gG, 256, SMEM_LAYER>>>(Hb, kw + 4 * 64 * 64, kb + 64, sw + 64 * 64, sb + 64, Ha, X16);

    // layer 2: Ha -> Hb (fp16 copy of Ha is in X16)
    k_lmv64h<<<gW, 256>>>(X16, nullptr, T1, T1h, 1.f, 0.f);
    k_lmv64h<<<gW, 256>>>(T1h, Ha, T2, T2h, 2.f, -1.f);
    k_lmv64h<<<gW, 256>>>(T2h, T1, T3, nullptr, 2.f, -1.f);
    k_layer<<<gG, 256, SMEM_LAYER>>>(Ha, kw + 8 * 64 * 64, kb + 128, sw + 2 * 64 * 64, sb + 128, Hb, X16);

    // mix head: A = [Hb|x]@W1, B = [Hb|x]@W0 + b; out = B + L(A)
    k_mixgemm<<<gM, 256, SMEM_MIX>>>(Hb, x, mw, mb);
    k_mixlmv<<<gW, 256>>>(outp);
}

// round 13
// speedup vs baseline: 1.3157x; 1.0807x over previous
#include <cuda_runtime.h>

#define NN 100000
#define NE 1200000
#define NB ((NN + 255) / 256)        // 391 scan blocks
#define NTILES (NN/32)               // 3125 (32-row GEMM tiles)

// ---------------- scratch (static device memory) ---------------------------
__device__ int    g_deg[NN];
__device__ int    g_cnt[NN];
__device__ int    g_fill[NN];
__device__ int    g_rp[NN + 1];
__device__ int    g_bsum[NB + 1];
__device__ float2 g_wc[NE];          // packed (weight, col-as-bits)
__device__ float  g_dinv[NN];
__device__ float  g_T1[NN * 64];
__device__ float  g_T2[NN * 64];
__device__ float  g_T3[NN * 64];
__device__ float  g_Ha[NN * 64];
__device__ float  g_Hb[NN * 64];
__device__ float  g_A[NN * 32];
__device__ float  g_B[NN * 32];

// ---------------- setup kernels --------------------------------------------
__global__ void k_zero3() {
    int i = blockIdx.x * blockDim.x + threadIdx.x;
    if (i < NN) { g_deg[i] = 0; g_cnt[i] = 0; g_fill[i] = 0; }
}

__global__ void k_degcnt(const int* __restrict__ src, const int* __restrict__ dst) {
    int i = blockIdx.x * blockDim.x + threadIdx.x;
    if (i < NE) {
        atomicAdd(&g_deg[src[i]], 1);
        atomicAdd(&g_cnt[dst[i]], 1);
    }
}

__global__ void k_dinv() {
    int i = blockIdx.x * blockDim.x + threadIdx.x;
    if (i < NN) {
        int d = g_deg[i];
        g_dinv[i] = (d > 0) ? rsqrtf((float)d) : 0.0f;
    }
}

// phase 1: per-block sums of g_cnt
__global__ void k_scan1() {
    __shared__ int s[8];
    const int t = threadIdx.x;
    int i = blockIdx.x * 256 + t;
    int v = (i < NN) ? g_cnt[i] : 0;
    #pragma unroll
    for (int d = 16; d; d >>= 1) v += __shfl_down_sync(0xffffffffu, v, d);
    if ((t & 31) == 0) s[t >> 5] = v;
    __syncthreads();
    if (t < 8) {
        int x = s[t];
        #pragma unroll
        for (int d = 4; d; d >>= 1) x += __shfl_down_sync(0xffu, x, d);
        if (t == 0) g_bsum[blockIdx.x] = x;
    }
}

// phase 2: exclusive scan of NB block sums (1 block, 512 threads)
__global__ void k_scan2() {
    __shared__ int wsum[16];
    const int t = threadIdx.x;
    int v = (t < NB) ? g_bsum[t] : 0;
    int xv = v;
    #pragma unroll
    for (int d = 1; d < 32; d <<= 1) {
        int y = __shfl_up_sync(0xffffffffu, xv, d);
        if ((t & 31) >= d) xv += y;
    }
    if ((t & 31) == 31) wsum[t >> 5] = xv;
    __syncthreads();
    if (t < 16) {
        int wv = wsum[t];
        int yv = wv;
        #pragma unroll
        for (int d = 1; d < 16; d <<= 1) {
            int z = __shfl_up_sync(0xffffu, yv, d);
            if (t >= d) yv += z;
        }
        wsum[t] = yv - wv;
    }
    __syncthreads();
    int incl = xv + wsum[t >> 5];
    int excl = incl - v;
    if (t < NB) g_bsum[t] = excl;
    if (t == NB - 1) g_rp[NN] = incl;
}

// phase 3: per-block exclusive scan + block offset
__global__ void k_scan3() {
    __shared__ int wsum[8];
    const int t = threadIdx.x;
    int i = blockIdx.x * 256 + t;
    int v = (i < NN) ? g_cnt[i] : 0;
    int xv = v;
    #pragma unroll
    for (int d = 1; d < 32; d <<= 1) {
        int y = __shfl_up_sync(0xffffffffu, xv, d);
        if ((t & 31) >= d) xv += y;
    }
    if ((t & 31) == 31) wsum[t >> 5] = xv;
    __syncthreads();
    if (t < 8) {
        int wv = wsum[t];
        int yv = wv;
        #pragma unroll
        for (int d = 1; d < 8; d <<= 1) {
            int z = __shfl_up_sync(0xffu, yv, d);
            if (t >= d) yv += z;
        }
        wsum[t] = yv - wv;
    }
    __syncthreads();
    if (i < NN) g_rp[i] = xv - v + wsum[t >> 5] + g_bsum[blockIdx.x];
}

__global__ void k_scatter(const int* __restrict__ src, const int* __restrict__ dst) {
    int i = blockIdx.x * blockDim.x + threadIdx.x;
    if (i < NE) {
        int s = src[i], d = dst[i];
        int pos = g_rp[d] + atomicAdd(&g_fill[d], 1);
        g_wc[pos] = make_float2(-g_dinv[s] * g_dinv[d], __int_as_float(s));
    }
}

// ---- sparse matvec: 2 nodes/warp, float4 gathers --------------------------
// out = alpha * (L z) + beta * sub, width 64
__global__ void k_lmv64(const float* __restrict__ z, const float* __restrict__ sub,
                        float* __restrict__ outp, float alpha, float beta) {
    int gt = blockIdx.x * blockDim.x + threadIdx.x;
    int warp = gt >> 5;
    int node = warp * 2 + ((gt >> 4) & 1);   // NN even: both halves valid together
    if (node >= NN) return;
    int l = gt & 15;                          // lane within half (0..15)
    int beg = g_rp[node], end = g_rp[node + 1];
    const float4* z4 = (const float4*)z;
    float4 acc = make_float4(0.f, 0.f, 0.f, 0.f);
    for (int e = beg; e < end; e++) {
        float2 p = g_wc[e];                   // broadcast within half-warp
        float4 v = z4[__float_as_int(p.y) * 16 + l];
        acc.x += p.x * v.x;
        acc.y += p.x * v.y;
        acc.z += p.x * v.z;
        acc.w += p.x * v.w;
    }
    float4 r;
    if (sub) {
        float4 sv = ((const float4*)sub)[node * 16 + l];
        r.x = alpha * acc.x + beta * sv.x;
        r.y = alpha * acc.y + beta * sv.y;
        r.z = alpha * acc.z + beta * sv.z;
        r.w = alpha * acc.w + beta * sv.w;
    } else {
        r.x = alpha * acc.x;
        r.y = alpha * acc.y;
        r.z = alpha * acc.z;
        r.w = alpha * acc.w;
    }
    ((float4*)outp)[node * 16 + l] = r;
}

// ---------------- fused layer GEMM -----------------------------------------
// out = relu([T0|T1|T2|T3] @ Wk + bk) + T0 @ Ws + bs
#define SMEM_LAYER (28928 * 4)
__global__ void __launch_bounds__(256, 2) k_layer(
        const float* __restrict__ T0,
        const float* __restrict__ Wk, const float* __restrict__ bk,
        const float* __restrict__ Ws, const float* __restrict__ bs,
        float* __restrict__ outp) {
    extern __shared__ float sm[];
    float* Wk_s = sm;            // 16384
    float* Ws_s = sm + 16384;    // 4096
    float* ins  = sm + 20480;    // 8192  [32 rows][256]
    float* bk_s = sm + 28672;    // 64
    float* bs_s = sm + 28736;    // 64
    const int t = threadIdx.x;   // 256 threads

    for (int j = t; j < 4096; j += 256) ((float4*)Wk_s)[j] = ((const float4*)Wk)[j];
    for (int j = t; j < 1024; j += 256) ((float4*)Ws_s)[j] = ((const float4*)Ws)[j];
    if (t < 64) { bk_s[t] = bk[t]; bs_s[t] = bs[t]; }

    const int cg = (t & 15) * 4;   // output col base (4 cols)
    const int r0 = (t >> 4) * 2;   // row base (2 rows)

    for (int tile = blockIdx.x; tile < NTILES; tile += gridDim.x) {
        const int rowbase = tile * 32;
        __syncthreads();
        {
            const float4* s0 = (const float4*)T0;
            const float4* s1 = (const float4*)g_T1;
            const float4* s2 = (const float4*)g_T2;
            const float4* s3 = (const float4*)g_T3;
            #pragma unroll
            for (int j = 0; j < 2; j++) {
                int i = t + j * 256;
                int r = i >> 4, f4 = i & 15;
                int gidx = (rowbase + r) * 16 + f4;
                *(float4*)&ins[r * 256 +   0 + f4 * 4] = s0[gidx];
                *(float4*)&ins[r * 256 +  64 + f4 * 4] = s1[gidx];
                *(float4*)&ins[r * 256 + 128 + f4 * 4] = s2[gidx];
                *(float4*)&ins[r * 256 + 192 + f4 * 4] = s3[gidx];
            }
        }
        __syncthreads();

        const float* in0 = &ins[r0 * 256];
        const float* in1 = in0 + 256;
        float4 acc0 = make_float4(0, 0, 0, 0), acc1 = acc0;
        #pragma unroll 8
        for (int kk = 0; kk < 256; kk++) {
            float4 wv = *(const float4*)&Wk_s[kk * 64 + cg];
            float a0 = in0[kk], a1 = in1[kk];
            acc0.x += a0 * wv.x; acc0.y += a0 * wv.y; acc0.z += a0 * wv.z; acc0.w += a0 * wv.w;
            acc1.x += a1 * wv.x; acc1.y += a1 * wv.y; acc1.z += a1 * wv.z; acc1.w += a1 * wv.w;
        }
        float4 sk0 = make_float4(0, 0, 0, 0), sk1 = sk0;
        #pragma unroll 8
        for (int kk = 0; kk < 64; kk++) {
            float4 wv = *(const float4*)&Ws_s[kk * 64 + cg];
            float a0 = in0[kk], a1 = in1[kk];
            sk0.x += a0 * wv.x; sk0.y += a0 * wv.y; sk0.z += a0 * wv.z; sk0.w += a0 * wv.w;
            sk1.x += a1 * wv.x; sk1.y += a1 * wv.y; sk1.z += a1 * wv.z; sk1.w += a1 * wv.w;
        }
        float4 bkv = *(const float4*)&bk_s[cg];
        float4 bsv = *(const float4*)&bs_s[cg];
        float4 o0, o1;
        o0.x = fmaxf(acc0.x + bkv.x, 0.f) + sk0.x + bsv.x;
        o0.y = fmaxf(acc0.y + bkv.y, 0.f) + sk0.y + bsv.y;
        o0.z = fmaxf(acc0.z + bkv.z, 0.f) + sk0.z + bsv.z;
        o0.w = fmaxf(acc0.w + bkv.w, 0.f) + sk0.w + bsv.w;
        o1.x = fmaxf(acc1.x + bkv.x, 0.f) + sk1.x + bsv.x;
        o1.y = fmaxf(acc1.y + bkv.y, 0.f) + sk1.y + bsv.y;
        o1.z = fmaxf(acc1.z + bkv.z, 0.f) + sk1.z + bsv.z;
        o1.w = fmaxf(acc1.w + bkv.w, 0.f) + sk1.w + bsv.w;
        *(float4*)&outp[(rowbase + r0) * 64 + cg]     = o0;
        *(float4*)&outp[(rowbase + r0 + 1) * 64 + cg] = o1;
    }
}

// ---------------- mix head GEMM: A = hc@W1, B = hc@W0 + b ------------------
#define SMEM_MIX (12320 * 4)
__global__ void __launch_bounds__(256, 4) k_mixgemm(
        const float* __restrict__ H, const float* __restrict__ x,
        const float* __restrict__ mw, const float* __restrict__ mb) {
    extern __shared__ float sm[];
    float* Wm_s = sm;           // 8192  [128][64]: cols 0..31 = W1, 32..63 = W0
    float* ins  = sm + 8192;    // 4096  [32 rows][128]
    float* mb_s = sm + 12288;   // 32
    const int t = threadIdx.x;

    for (int j = t; j < 8192; j += 256) {
        int f = j >> 6, col = j & 63;
        Wm_s[j] = (col < 32) ? mw[128 * 32 + f * 32 + col] : mw[f * 32 + (col - 32)];
    }
    if (t < 32) mb_s[t] = mb[t];

    const int cg = (t & 15) * 4;
    const int r0 = (t >> 4) * 2;

    for (int tile = blockIdx.x; tile < NTILES; tile += gridDim.x) {
        const int rowbase = tile * 32;
        __syncthreads();
        {
            const float4* sH = (const float4*)H;
            const float4* sx = (const float4*)x;
            #pragma unroll
            for (int j = 0; j < 2; j++) {
                int i = t + j * 256;
                int r = i >> 4, f4 = i & 15;
                int gidx = (rowbase + r) * 16 + f4;
                *(float4*)&ins[r * 128 +      f4 * 4] = sH[gidx];
                *(float4*)&ins[r * 128 + 64 + f4 * 4] = sx[gidx];
            }
        }
        __syncthreads();

        const float* in0 = &ins[r0 * 128];
        const float* in1 = in0 + 128;
        float4 acc0 = make_float4(0, 0, 0, 0), acc1 = acc0;
        #pragma unroll 8
        for (int kk = 0; kk < 128; kk++) {
            float4 wv = *(const float4*)&Wm_s[kk * 64 + cg];
            float a0 = in0[kk], a1 = in1[kk];
            acc0.x += a0 * wv.x; acc0.y += a0 * wv.y; acc0.z += a0 * wv.z; acc0.w += a0 * wv.w;
            acc1.x += a1 * wv.x; acc1.y += a1 * wv.y; acc1.z += a1 * wv.z; acc1.w += a1 * wv.w;
        }
        if (cg < 32) {
            *(float4*)&g_A[(rowbase + r0) * 32 + cg]     = acc0;
            *(float4*)&g_A[(rowbase + r0 + 1) * 32 + cg] = acc1;
        } else {
            float4 bv = *(const float4*)&mb_s[cg - 32];
            acc0.x += bv.x; acc0.y += bv.y; acc0.z += bv.z; acc0.w += bv.w;
            acc1.x += bv.x; acc1.y += bv.y; acc1.z += bv.z; acc1.w += bv.w;
            *(float4*)&g_B[(rowbase + r0) * 32 + cg - 32]     = acc0;
            *(float4*)&g_B[(rowbase + r0 + 1) * 32 + cg - 32] = acc1;
        }
    }
}

// ---- final: out = B + L(A), width 32; 4 nodes/warp, float4 gathers --------
__global__ void k_mixlmv(float* __restrict__ outp) {
    int gt = blockIdx.x * blockDim.x + threadIdx.x;
    int warp = gt >> 5;
    int node = warp * 4 + ((gt >> 3) & 3);   // NN % 4 == 0
    if (node >= NN) return;
    int l = gt & 7;                           // lane within quarter (0..7)
    int beg = g_rp[node], end = g_rp[node + 1];
    const float4* A4 = (const float4*)g_A;
    float4 acc = make_float4(0.f, 0.f, 0.f, 0.f);
    for (int e = beg; e < end; e++) {
        float2 p = g_wc[e];
        float4 v = A4[__float_as_int(p.y) * 8 + l];
        acc.x += p.x * v.x;
        acc.y += p.x * v.y;
        acc.z += p.x * v.z;
        acc.w += p.x * v.w;
    }
    float4 bv = ((const float4*)g_B)[node * 8 + l];
    float4 r = make_float4(bv.x + acc.x, bv.y + acc.y, bv.z + acc.z, bv.w + acc.w);
    ((float4*)outp)[node * 8 + l] = r;
}

// ---------------- launch ---------------------------------------------------
extern "C" void kernel_launch(void* const* d_in, const int* in_sizes, int n_in,
                              void* d_out, int out_size) {
    const float* x  = (const float*)d_in[0];
    const int*   ei = (const int*)d_in[1];
    const float* kw = (const float*)d_in[2];   // [3][4][64][64]
    const float* kb = (const float*)d_in[3];   // [3][64]
    const float* sw = (const float*)d_in[4];   // [3][64][64]
    const float* sb = (const float*)d_in[5];   // [3][64]
    const float* mw = (const float*)d_in[6];   // [2][128][32]
    const float* mb = (const float*)d_in[7];   // [32]
    float* outp = (float*)d_out;
    const int* src = ei;
    const int* dst = ei + NE;

    float *T1, *T2, *T3, *Ha, *Hb;
    cudaGetSymbolAddress((void**)&T1, g_T1);
    cudaGetSymbolAddress((void**)&T2, g_T2);
    cudaGetSymbolAddress((void**)&T3, g_T3);
    cudaGetSymbolAddress((void**)&Ha, g_Ha);
    cudaGetSymbolAddress((void**)&Hb, g_Hb);

    cudaFuncSetAttribute(k_layer, cudaFuncAttributeMaxDynamicSharedMemorySize, SMEM_LAYER);
    cudaFuncSetAttribute(k_mixgemm, cudaFuncAttributeMaxDynamicSharedMemorySize, SMEM_MIX);

    const int gE = (NE + 255) / 256;            // 4688
    const int gN = NB;                          // 391
    const int gW = (NN / 2 * 32 + 255) / 256;   // 6250 (2 nodes per warp)
    const int gX = (NN / 4 * 32 + 255) / 256;   // 3125 (4 nodes per warp)
    const int gG = 296;                         // k_layer: 2 blocks/SM target
    const int gM = 592;                         // mixgemm grid

    // graph setup: degrees, dinv, CSR by dst
    k_zero3<<<gN, 256>>>();
    k_degcnt<<<gE, 256>>>(src, dst);
    k_dinv<<<gN, 256>>>();
    k_scan1<<<gN, 256>>>();
    k_scan2<<<1, 512>>>();
    k_scan3<<<gN, 256>>>();
    k_scatter<<<gE, 256>>>(src, dst);

    // layer 0: input = x, output = Hb
    k_lmv64<<<gW, 256>>>(x, nullptr, T1, 1.f, 0.f);
    k_lmv64<<<gW, 256>>>(T1, x, T2, 2.f, -1.f);
    k_lmv64<<<gW, 256>>>(T2, T1, T3, 2.f, -1.f);
    k_layer<<<gG, 256, SMEM_LAYER>>>(x, kw, kb, sw, sb, Hb);

    // layer 1: Hb -> Ha
    k_lmv64<<<gW, 256>>>(Hb, nullptr, T1, 1.f, 0.f);
    k_lmv64<<<gW, 256>>>(T1, Hb, T2, 2.f, -1.f);
    k_lmv64<<<gW, 256>>>(T2, T1, T3, 2.f, -1.f);
    k_layer<<<gG, 256, SMEM_LAYER>>>(Hb, kw + 4 * 64 * 64, kb + 64, sw + 64 * 64, sb + 64, Ha);

    // layer 2: Ha -> Hb
    k_lmv64<<<gW, 256>>>(Ha, nullptr, T1, 1.f, 0.f);
    k_lmv64<<<gW, 256>>>(T1, Ha, T2, 2.f, -1.f);
    k_lmv64<<<gW, 256>>>(T2, T1, T3, 2.f, -1.f);
    k_layer<<<gG, 256, SMEM_LAYER>>>(Ha, kw + 8 * 64 * 64, kb + 128, sw + 2 * 64 * 64, sb + 128, Hb);

    // mix head: A = [Hb|x]@W1, B = [Hb|x]@W0 + b; out = B + L(A)
    k_mixgemm<<<gM, 256, SMEM_MIX>>>(Hb, x, mw, mb);
    k_mixlmv<<<gX, 256>>>(outp);
}

// round 14
// speedup vs baseline: 1.3804x; 1.0492x over previous
#include <cuda_runtime.h>
#include <cuda_fp16.h>
#include <cstdint>

#define NN 100000
#define NE 1200000
#define NB ((NN + 255) / 256)        // 391 scan blocks
#define NTILES (NN/32)               // 3125 (32-row GEMM tiles)

// ---------------- scratch (static device memory) ---------------------------
__device__ int    g_deg[NN];
__device__ int    g_cnt[NN];
__device__ int    g_fill[NN];
__device__ int    g_rp[NN + 1];
__device__ int    g_bsum[NB + 1];
__device__ float2 g_wc[NE];          // packed (weight, col-as-bits)
__device__ float  g_dinv[NN];
__device__ __half2 g_T1h[NN * 32];   // fp16 Chebyshev terms (64 halfs/row)
__device__ __half2 g_T2h[NN * 32];
__device__ __half2 g_T3h[NN * 32];
__device__ __half2 g_Hh[NN * 32];    // fp16 copy of current layer input
__device__ float  g_Ha[NN * 64];
__device__ float  g_Hb[NN * 64];
__device__ float  g_A[NN * 32];
__device__ float  g_B[NN * 32];

// ---------------- setup kernels --------------------------------------------
__global__ void k_zero3() {
    int i = blockIdx.x * blockDim.x + threadIdx.x;
    if (i < NN) { g_deg[i] = 0; g_cnt[i] = 0; g_fill[i] = 0; }
}

__global__ void k_degcnt(const int* __restrict__ src, const int* __restrict__ dst) {
    int i = blockIdx.x * blockDim.x + threadIdx.x;
    if (i < NE) {
        atomicAdd(&g_deg[src[i]], 1);
        atomicAdd(&g_cnt[dst[i]], 1);
    }
}

__global__ void k_dinv() {
    int i = blockIdx.x * blockDim.x + threadIdx.x;
    if (i < NN) {
        int d = g_deg[i];
        g_dinv[i] = (d > 0) ? rsqrtf((float)d) : 0.0f;
    }
}

// convert fp32 feature array (width 64) to fp16 g_Hh
__global__ void k_tohalf(const float* __restrict__ z) {
    int i = blockIdx.x * blockDim.x + threadIdx.x;
    if (i < NN * 16) {
        float4 v = ((const float4*)z)[i];
        uint2 u;
        __half2 h0 = __floats2half2_rn(v.x, v.y);
        __half2 h1 = __floats2half2_rn(v.z, v.w);
        u.x = *(uint32_t*)&h0;
        u.y = *(uint32_t*)&h1;
        ((uint2*)g_Hh)[i] = u;
    }
}

__global__ void k_scan1() {
    __shared__ int s[8];
    const int t = threadIdx.x;
    int i = blockIdx.x * 256 + t;
    int v = (i < NN) ? g_cnt[i] : 0;
    #pragma unroll
    for (int d = 16; d; d >>= 1) v += __shfl_down_sync(0xffffffffu, v, d);
    if ((t & 31) == 0) s[t >> 5] = v;
    __syncthreads();
    if (t < 8) {
        int x = s[t];
        #pragma unroll
        for (int d = 4; d; d >>= 1) x += __shfl_down_sync(0xffu, x, d);
        if (t == 0) g_bsum[blockIdx.x] = x;
    }
}

__global__ void k_scan2() {
    __shared__ int wsum[16];
    const int t = threadIdx.x;
    int v = (t < NB) ? g_bsum[t] : 0;
    int xv = v;
    #pragma unroll
    for (int d = 1; d < 32; d <<= 1) {
        int y = __shfl_up_sync(0xffffffffu, xv, d);
        if ((t & 31) >= d) xv += y;
    }
    if ((t & 31) == 31) wsum[t >> 5] = xv;
    __syncthreads();
    if (t < 16) {
        int wv = wsum[t];
        int yv = wv;
        #pragma unroll
        for (int d = 1; d < 16; d <<= 1) {
            int z = __shfl_up_sync(0xffffu, yv, d);
            if (t >= d) yv += z;
        }
        wsum[t] = yv - wv;
    }
    __syncthreads();
    int incl = xv + wsum[t >> 5];
    int excl = incl - v;
    if (t < NB) g_bsum[t] = excl;
    if (t == NB - 1) g_rp[NN] = incl;
}

__global__ void k_scan3() {
    __shared__ int wsum[8];
    const int t = threadIdx.x;
    int i = blockIdx.x * 256 + t;
    int v = (i < NN) ? g_cnt[i] : 0;
    int xv = v;
    #pragma unroll
    for (int d = 1; d < 32; d <<= 1) {
        int y = __shfl_up_sync(0xffffffffu, xv, d);
        if ((t & 31) >= d) xv += y;
    }
    if ((t & 31) == 31) wsum[t >> 5] = xv;
    __syncthreads();
    if (t < 8) {
        int wv = wsum[t];
        int yv = wv;
        #pragma unroll
        for (int d = 1; d < 8; d <<= 1) {
            int z = __shfl_up_sync(0xffu, yv, d);
            if (t >= d) yv += z;
        }
        wsum[t] = yv - wv;
    }
    __syncthreads();
    if (i < NN) g_rp[i] = xv - v + wsum[t >> 5] + g_bsum[blockIdx.x];
}

__global__ void k_scatter(const int* __restrict__ src, const int* __restrict__ dst) {
    int i = blockIdx.x * blockDim.x + threadIdx.x;
    if (i < NE) {
        int s = src[i], d = dst[i];
        int pos = g_rp[d] + atomicAdd(&g_fill[d], 1);
        g_wc[pos] = make_float2(-g_dinv[s] * g_dinv[d], __int_as_float(s));
    }
}

// ---- fp16 sparse matvec: 2 nodes/warp, 8B gathers -------------------------
// out = alpha * (L zh) + beta * subh  (fp32 accumulate, fp16 store)
__global__ void k_lmvh(const __half2* __restrict__ zh, const __half2* __restrict__ subh,
                       __half2* __restrict__ outh, float alpha, float beta) {
    int gt = blockIdx.x * blockDim.x + threadIdx.x;
    int warp = gt >> 5;
    int node = warp * 2 + ((gt >> 4) & 1);   // NN even
    if (node >= NN) return;
    int l = gt & 15;                          // lane within half (0..15), 4 features
    int beg = g_rp[node], end = g_rp[node + 1];
    const uint2* z2 = (const uint2*)zh;
    float2 a0 = make_float2(0.f, 0.f), a1 = a0;
    for (int e = beg; e < end; e++) {
        float2 p = g_wc[e];
        uint2 v = z2[__float_as_int(p.y) * 16 + l];
        float2 f0 = __half22float2(*(__half2*)&v.x);
        float2 f1 = __half22float2(*(__half2*)&v.y);
        a0.x += p.x * f0.x; a0.y += p.x * f0.y;
        a1.x += p.x * f1.x; a1.y += p.x * f1.y;
    }
    float4 r;
    if (subh) {
        uint2 sv = ((const uint2*)subh)[node * 16 + l];
        float2 s0 = __half22float2(*(__half2*)&sv.x);
        float2 s1 = __half22float2(*(__half2*)&sv.y);
        r.x = alpha * a0.x + beta * s0.x;
        r.y = alpha * a0.y + beta * s0.y;
        r.z = alpha * a1.x + beta * s1.x;
        r.w = alpha * a1.y + beta * s1.y;
    } else {
        r.x = alpha * a0.x;
        r.y = alpha * a0.y;
        r.z = alpha * a1.x;
        r.w = alpha * a1.y;
    }
    uint2 o;
    __half2 h0 = __floats2half2_rn(r.x, r.y);
    __half2 h1 = __floats2half2_rn(r.z, r.w);
    o.x = *(uint32_t*)&h0;
    o.y = *(uint32_t*)&h1;
    ((uint2*)outh)[node * 16 + l] = o;
}

// ---------------- fused layer GEMM -----------------------------------------
// out = relu([T0|T1|T2|T3] @ Wk + bk) + T0 @ Ws + bs ; also fp16 copy -> g_Hh
#define SMEM_LAYER (28928 * 4)
__global__ void __launch_bounds__(256, 2) k_layer(
        const float* __restrict__ T0,
        const float* __restrict__ Wk, const float* __restrict__ bk,
        const float* __restrict__ Ws, const float* __restrict__ bs,
        float* __restrict__ outp) {
    extern __shared__ float sm[];
    float* Wk_s = sm;            // 16384
    float* Ws_s = sm + 16384;    // 4096
    float* ins  = sm + 20480;    // 8192  [32 rows][256]
    float* bk_s = sm + 28672;    // 64
    float* bs_s = sm + 28736;    // 64
    const int t = threadIdx.x;   // 256 threads

    for (int j = t; j < 4096; j += 256) ((float4*)Wk_s)[j] = ((const float4*)Wk)[j];
    for (int j = t; j < 1024; j += 256) ((float4*)Ws_s)[j] = ((const float4*)Ws)[j];
    if (t < 64) { bk_s[t] = bk[t]; bs_s[t] = bs[t]; }

    const int cg = (t & 15) * 4;   // output col base (4 cols)
    const int r0 = (t >> 4) * 2;   // row base (2 rows)

    for (int tile = blockIdx.x; tile < NTILES; tile += gridDim.x) {
        const int rowbase = tile * 32;
        __syncthreads();
        {
            const float4* s0 = (const float4*)T0;
            const uint2* h1 = (const uint2*)g_T1h;
            const uint2* h2 = (const uint2*)g_T2h;
            const uint2* h3 = (const uint2*)g_T3h;
            #pragma unroll
            for (int j = 0; j < 2; j++) {
                int i = t + j * 256;
                int r = i >> 4, f4 = i & 15;
                int gidx = (rowbase + r) * 16 + f4;
                *(float4*)&ins[r * 256 + 0 + f4 * 4] = s0[gidx];
                uint2 u1 = h1[gidx], u2 = h2[gidx], u3 = h3[gidx];
                float2 a, b;
                a = __half22float2(*(__half2*)&u1.x);
                b = __half22float2(*(__half2*)&u1.y);
                *(float4*)&ins[r * 256 +  64 + f4 * 4] = make_float4(a.x, a.y, b.x, b.y);
                a = __half22float2(*(__half2*)&u2.x);
                b = __half22float2(*(__half2*)&u2.y);
                *(float4*)&ins[r * 256 + 128 + f4 * 4] = make_float4(a.x, a.y, b.x, b.y);
                a = __half22float2(*(__half2*)&u3.x);
                b = __half22float2(*(__half2*)&u3.y);
                *(float4*)&ins[r * 256 + 192 + f4 * 4] = make_float4(a.x, a.y, b.x, b.y);
            }
        }
        __syncthreads();

        const float* in0 = &ins[r0 * 256];
        const float* in1 = in0 + 256;
        float4 acc0 = make_float4(0, 0, 0, 0), acc1 = acc0;
        #pragma unroll 8
        for (int kk = 0; kk < 256; kk++) {
            float4 wv = *(const float4*)&Wk_s[kk * 64 + cg];
            float a0 = in0[kk], a1 = in1[kk];
            acc0.x += a0 * wv.x; acc0.y += a0 * wv.y; acc0.z += a0 * wv.z; acc0.w += a0 * wv.w;
            acc1.x += a1 * wv.x; acc1.y += a1 * wv.y; acc1.z += a1 * wv.z; acc1.w += a1 * wv.w;
        }
        float4 sk0 = make_float4(0, 0, 0, 0), sk1 = sk0;
        #pragma unroll 8
        for (int kk = 0; kk < 64; kk++) {
            float4 wv = *(const float4*)&Ws_s[kk * 64 + cg];
            float a0 = in0[kk], a1 = in1[kk];
            sk0.x += a0 * wv.x; sk0.y += a0 * wv.y; sk0.z += a0 * wv.z; sk0.w += a0 * wv.w;
            sk1.x += a1 * wv.x; sk1.y += a1 * wv.y; sk1.z += a1 * wv.z; sk1.w += a1 * wv.w;
        }
        float4 bkv = *(const float4*)&bk_s[cg];
        float4 bsv = *(const float4*)&bs_s[cg];
        float4 o0, o1;
        o0.x = fmaxf(acc0.x + bkv.x, 0.f) + sk0.x + bsv.x;
        o0.y = fmaxf(acc0.y + bkv.y, 0.f) + sk0.y + bsv.y;
        o0.z = fmaxf(acc0.z + bkv.z, 0.f) + sk0.z + bsv.z;
        o0.w = fmaxf(acc0.w + bkv.w, 0.f) + sk0.w + bsv.w;
        o1.x = fmaxf(acc1.x + bkv.x, 0.f) + sk1.x + bsv.x;
        o1.y = fmaxf(acc1.y + bkv.y, 0.f) + sk1.y + bsv.y;
        o1.z = fmaxf(acc1.z + bkv.z, 0.f) + sk1.z + bsv.z;
        o1.w = fmaxf(acc1.w + bkv.w, 0.f) + sk1.w + bsv.w;
        const int ro0 = rowbase + r0, ro1 = ro0 + 1;
        *(float4*)&outp[ro0 * 64 + cg] = o0;
        *(float4*)&outp[ro1 * 64 + cg] = o1;
        uint2 u;
        __half2 hh0 = __floats2half2_rn(o0.x, o0.y);
        __half2 hh1 = __floats2half2_rn(o0.z, o0.w);
        u.x = *(uint32_t*)&hh0; u.y = *(uint32_t*)&hh1;
        ((uint2*)g_Hh)[ro0 * 16 + (cg >> 2)] = u;
        hh0 = __floats2half2_rn(o1.x, o1.y);
        hh1 = __floats2half2_rn(o1.z, o1.w);
        u.x = *(uint32_t*)&hh0; u.y = *(uint32_t*)&hh1;
        ((uint2*)g_Hh)[ro1 * 16 + (cg >> 2)] = u;
    }
}

// ---------------- mix head GEMM: A = hc@W1, B = hc@W0 + b ------------------
#define SMEM_MIX (12320 * 4)
__global__ void __launch_bounds__(256, 4) k_mixgemm(
        const float* __restrict__ H, const float* __restrict__ x,
        const float* __restrict__ mw, const float* __restrict__ mb) {
    extern __shared__ float sm[];
    float* Wm_s = sm;           // 8192  [128][64]: cols 0..31 = W1, 32..63 = W0
    float* ins  = sm + 8192;    // 4096  [32 rows][128]
    float* mb_s = sm + 12288;   // 32
    const int t = threadIdx.x;

    for (int j = t; j < 8192; j += 256) {
        int f = j >> 6, col = j & 63;
        Wm_s[j] = (col < 32) ? mw[128 * 32 + f * 32 + col] : mw[f * 32 + (col - 32)];
    }
    if (t < 32) mb_s[t] = mb[t];

    const int cg = (t & 15) * 4;
    const int r0 = (t >> 4) * 2;

    for (int tile = blockIdx.x; tile < NTILES; tile += gridDim.x) {
        const int rowbase = tile * 32;
        __syncthreads();
        {
            const float4* sH = (const float4*)H;
            const float4* sx = (const float4*)x;
            #pragma unroll
            for (int j = 0; j < 2; j++) {
                int i = t + j * 256;
                int r = i >> 4, f4 = i & 15;
                int gidx = (rowbase + r) * 16 + f4;
                *(float4*)&ins[r * 128 +      f4 * 4] = sH[gidx];
                *(float4*)&ins[r * 128 + 64 + f4 * 4] = sx[gidx];
            }
        }
        __syncthreads();

        const float* in0 = &ins[r0 * 128];
        const float* in1 = in0 + 128;
        float4 acc0 = make_float4(0, 0, 0, 0), acc1 = acc0;
        #pragma unroll 8
        for (int kk = 0; kk < 128; kk++) {
            float4 wv = *(const float4*)&Wm_s[kk * 64 + cg];
            float a0 = in0[kk], a1 = in1[kk];
            acc0.x += a0 * wv.x; acc0.y += a0 * wv.y; acc0.z += a0 * wv.z; acc0.w += a0 * wv.w;
            acc1.x += a1 * wv.x; acc1.y += a1 * wv.y; acc1.z += a1 * wv.z; acc1.w += a1 * wv.w;
        }
        if (cg < 32) {
            *(float4*)&g_A[(rowbase + r0) * 32 + cg]     = acc0;
            *(float4*)&g_A[(rowbase + r0 + 1) * 32 + cg] = acc1;
        } else {
            float4 bv = *(const float4*)&mb_s[cg - 32];
            acc0.x += bv.x; acc0.y += bv.y; acc0.z += bv.z; acc0.w += bv.w;
            acc1.x += bv.x; acc1.y += bv.y; acc1.z += bv.z; acc1.w += bv.w;
            *(float4*)&g_B[(rowbase + r0) * 32 + cg - 32]     = acc0;
            *(float4*)&g_B[(rowbase + r0 + 1) * 32 + cg - 32] = acc1;
        }
    }
}

// ---- final: out = B + L(A), width 32; 4 nodes/warp, float4 gathers --------
__global__ void k_mixlmv(float* __restrict__ outp) {
    int gt = blockIdx.x * blockDim.x + threadIdx.x;
    int warp = gt >> 5;
    int node = warp * 4 + ((gt >> 3) & 3);   // NN % 4 == 0
    if (node >= NN) return;
    int l = gt & 7;                           // lane within quarter (0..7)
    int beg = g_rp[node], end = g_rp[node + 1];
    const float4* A4 = (const float4*)g_A;
    float4 acc = make_float4(0.f, 0.f, 0.f, 0.f);
    for (int e = beg; e < end; e++) {
        float2 p = g_wc[e];
        float4 v = A4[__float_as_int(p.y) * 8 + l];
        acc.x += p.x * v.x;
        acc.y += p.x * v.y;
        acc.z += p.x * v.z;
        acc.w += p.x * v.w;
    }
    float4 bv = ((const float4*)g_B)[node * 8 + l];
    float4 r = make_float4(bv.x + acc.x, bv.y + acc.y, bv.z + acc.z, bv.w + acc.w);
    ((float4*)outp)[node * 8 + l] = r;
}

// ---------------- launch ---------------------------------------------------
extern "C" void kernel_launch(void* const* d_in, const int* in_sizes, int n_in,
                              void* d_out, int out_size) {
    const float* x  = (const float*)d_in[0];
    const int*   ei = (const int*)d_in[1];
    const float* kw = (const float*)d_in[2];   // [3][4][64][64]
    const float* kb = (const float*)d_in[3];   // [3][64]
    const float* sw = (const float*)d_in[4];   // [3][64][64]
    const float* sb = (const float*)d_in[5];   // [3][64]
    const float* mw = (const float*)d_in[6];   // [2][128][32]
    const float* mb = (const float*)d_in[7];   // [32]
    float* outp = (float*)d_out;
    const int* src = ei;
    const int* dst = ei + NE;

    float *Ha, *Hb;
    __half2 *T1h, *T2h, *T3h, *Hh;
    cudaGetSymbolAddress((void**)&Ha, g_Ha);
    cudaGetSymbolAddress((void**)&Hb, g_Hb);
    cudaGetSymbolAddress((void**)&T1h, g_T1h);
    cudaGetSymbolAddress((void**)&T2h, g_T2h);
    cudaGetSymbolAddress((void**)&T3h, g_T3h);
    cudaGetSymbolAddress((void**)&Hh, g_Hh);

    cudaFuncSetAttribute(k_layer, cudaFuncAttributeMaxDynamicSharedMemorySize, SMEM_LAYER);
    cudaFuncSetAttribute(k_mixgemm, cudaFuncAttributeMaxDynamicSharedMemorySize, SMEM_MIX);

    const int gE = (NE + 255) / 256;            // 4688
    const int gN = NB;                          // 391
    const int gH = (NN * 16 + 255) / 256;       // 6250 (tohalf elements)
    const int gW = (NN / 2 * 32 + 255) / 256;   // 6250 (2 nodes per warp)
    const int gX = (NN / 4 * 32 + 255) / 256;   // 3125 (4 nodes per warp)
    const int gG = 296;                         // k_layer grid
    const int gM = 592;                         // mixgemm grid

    // graph setup: degrees, dinv, CSR by dst; fp16 copy of x
    k_zero3<<<gN, 256>>>();
    k_degcnt<<<gE, 256>>>(src, dst);
    k_dinv<<<gN, 256>>>();
    k_scan1<<<gN, 256>>>();
    k_scan2<<<1, 512>>>();
    k_scan3<<<gN, 256>>>();
    k_scatter<<<gE, 256>>>(src, dst);
    k_tohalf<<<gH, 256>>>(x);

    // layer 0: input = x (fp16 copy in g_Hh), output = Hb (+g_Hh)
    k_lmvh<<<gW, 256>>>(Hh, nullptr, T1h, 1.f, 0.f);
    k_lmvh<<<gW, 256>>>(T1h, Hh, T2h, 2.f, -1.f);
    k_lmvh<<<gW, 256>>>(T2h, T1h, T3h, 2.f, -1.f);
    k_layer<<<gG, 256, SMEM_LAYER>>>(x, kw, kb, sw, sb, Hb);

    // layer 1: Hb -> Ha
    k_lmvh<<<gW, 256>>>(Hh, nullptr, T1h, 1.f, 0.f);
    k_lmvh<<<gW, 256>>>(T1h, Hh, T2h, 2.f, -1.f);
    k_lmvh<<<gW, 256>>>(T2h, T1h, T3h, 2.f, -1.f);
    k_layer<<<gG, 256, SMEM_LAYER>>>(Hb, kw + 4 * 64 * 64, kb + 64, sw + 64 * 64, sb + 64, Ha);

    // layer 2: Ha -> Hb
    k_lmvh<<<gW, 256>>>(Hh, nullptr, T1h, 1.f, 0.f);
    k_lmvh<<<gW, 256>>>(T1h, Hh, T2h, 2.f, -1.f);
    k_lmvh<<<gW, 256>>>(T2h, T1h, T3h, 2.f, -1.f);
    k_layer<<<gG, 256, SMEM_LAYER>>>(Ha, kw + 8 * 64 * 64, kb + 128, sw + 2 * 64 * 64, sb + 128, Hb);

    // mix head: A = [Hb|x]@W1, B = [Hb|x]@W0 + b; out = B + L(A)
    k_mixgemm<<<gM, 256, SMEM_MIX>>>(Hb, x, mw, mb);
    k_mixlmv<<<gX, 256>>>(outp);
}

// round 17
// speedup vs baseline: 1.4389x; 1.0423x over previous
#include <cuda_runtime.h>
#include <cuda_fp16.h>
#include <cstdint>

#define NN 100000
#define NE 1200000
#define NB ((NN + 255) / 256)        // 391 scan blocks
#define NTILES (NN/32)               // 3125 (32-row GEMM tiles)

// ---------------- scratch (static device memory) ---------------------------
__device__ int    g_deg[NN];
__device__ int    g_cnt[NN];
__device__ int    g_fill[NN];
__device__ int    g_rp[NN + 1];
__device__ int    g_bsum[NB + 1];
__device__ float2 g_wc[NE];          // packed (weight, col-as-bits)
__device__ float  g_dinv[NN];
__device__ __half2 g_T1h[NN * 32];   // fp16 Chebyshev terms (64 halfs/row)
__device__ __half2 g_T2h[NN * 32];
__device__ __half2 g_T3h[NN * 32];
__device__ __half2 g_Hh[NN * 32];    // fp16 copy of current layer input
__device__ float  g_Ha[NN * 64];
__device__ float  g_Hb[NN * 64];
__device__ float  g_A[NN * 32];
__device__ float  g_B[NN * 32];

// ---------------- setup kernels --------------------------------------------
__global__ void k_zero3() {
    int i = blockIdx.x * blockDim.x + threadIdx.x;
    if (i < NN) { g_deg[i] = 0; g_cnt[i] = 0; g_fill[i] = 0; }
}

__global__ void k_degcnt(const int* __restrict__ src, const int* __restrict__ dst) {
    int i = blockIdx.x * blockDim.x + threadIdx.x;
    if (i < NE) {
        atomicAdd(&g_deg[src[i]], 1);
        atomicAdd(&g_cnt[dst[i]], 1);
    }
}

__global__ void k_dinv() {
    int i = blockIdx.x * blockDim.x + threadIdx.x;
    if (i < NN) {
        int d = g_deg[i];
        g_dinv[i] = (d > 0) ? rsqrtf((float)d) : 0.0f;
    }
}

// convert fp32 feature array (width 64) to fp16 g_Hh
__global__ void k_tohalf(const float* __restrict__ z) {
    int i = blockIdx.x * blockDim.x + threadIdx.x;
    if (i < NN * 16) {
        float4 v = ((const float4*)z)[i];
        uint2 u;
        __half2 h0 = __floats2half2_rn(v.x, v.y);
        __half2 h1 = __floats2half2_rn(v.z, v.w);
        u.x = *(uint32_t*)&h0;
        u.y = *(uint32_t*)&h1;
        ((uint2*)g_Hh)[i] = u;
    }
}

__global__ void k_scan1() {
    __shared__ int s[8];
    const int t = threadIdx.x;
    int i = blockIdx.x * 256 + t;
    int v = (i < NN) ? g_cnt[i] : 0;
    #pragma unroll
    for (int d = 16; d; d >>= 1) v += __shfl_down_sync(0xffffffffu, v, d);
    if ((t & 31) == 0) s[t >> 5] = v;
    __syncthreads();
    if (t < 8) {
        int x = s[t];
        #pragma unroll
        for (int d = 4; d; d >>= 1) x += __shfl_down_sync(0xffu, x, d);
        if (t == 0) g_bsum[blockIdx.x] = x;
    }
}

__global__ void k_scan2() {
    __shared__ int wsum[16];
    const int t = threadIdx.x;
    int v = (t < NB) ? g_bsum[t] : 0;
    int xv = v;
    #pragma unroll
    for (int d = 1; d < 32; d <<= 1) {
        int y = __shfl_up_sync(0xffffffffu, xv, d);
        if ((t & 31) >= d) xv += y;
    }
    if ((t & 31) == 31) wsum[t >> 5] = xv;
    __syncthreads();
    if (t < 16) {
        int wv = wsum[t];
        int yv = wv;
        #pragma unroll
        for (int d = 1; d < 16; d <<= 1) {
            int z = __shfl_up_sync(0xffffu, yv, d);
            if (t >= d) yv += z;
        }
        wsum[t] = yv - wv;
    }
    __syncthreads();
    int incl = xv + wsum[t >> 5];
    int excl = incl - v;
    if (t < NB) g_bsum[t] = excl;
    if (t == NB - 1) g_rp[NN] = incl;
}

__global__ void k_scan3() {
    __shared__ int wsum[8];
    const int t = threadIdx.x;
    int i = blockIdx.x * 256 + t;
    int v = (i < NN) ? g_cnt[i] : 0;
    int xv = v;
    #pragma unroll
    for (int d = 1; d < 32; d <<= 1) {
        int y = __shfl_up_sync(0xffffffffu, xv, d);
        if ((t & 31) >= d) xv += y;
    }
    if ((t & 31) == 31) wsum[t >> 5] = xv;
    __syncthreads();
    if (t < 8) {
        int wv = wsum[t];
        int yv = wv;
        #pragma unroll
        for (int d = 1; d < 8; d <<= 1) {
            int z = __shfl_up_sync(0xffu, yv, d);
            if (t >= d) yv += z;
        }
        wsum[t] = yv - wv;
    }
    __syncthreads();
    if (i < NN) g_rp[i] = xv - v + wsum[t >> 5] + g_bsum[blockIdx.x];
}

__global__ void k_scatter(const int* __restrict__ src, const int* __restrict__ dst) {
    int i = blockIdx.x * blockDim.x + threadIdx.x;
    if (i < NE) {
        int s = src[i], d = dst[i];
        int pos = g_rp[d] + atomicAdd(&g_fill[d], 1);
        g_wc[pos] = make_float2(-g_dinv[s] * g_dinv[d], __int_as_float(s));
    }
}

// ---- fp16 sparse matvec: 4 nodes/warp, 16B gathers ------------------------
// out = alpha * (L zh) + beta * subh  (fp32 accumulate, fp16 store)
__global__ void k_lmvh(const __half2* __restrict__ zh, const __half2* __restrict__ subh,
                       __half2* __restrict__ outh, float alpha, float beta) {
    int gt = blockIdx.x * blockDim.x + threadIdx.x;
    int warp = gt >> 5;
    int node = warp * 4 + ((gt >> 3) & 3);   // NN % 4 == 0
    if (node >= NN) return;
    int l = gt & 7;                           // lane within quarter: 8 halfs (16B)
    int beg = g_rp[node], end = g_rp[node + 1];
    const uint4* z4 = (const uint4*)zh;
    float2 a0 = make_float2(0.f, 0.f), a1 = a0, a2 = a0, a3 = a0;
    for (int e = beg; e < end; e++) {
        float2 p = g_wc[e];                   // broadcast within quarter
        uint4 v = z4[__float_as_int(p.y) * 8 + l];
        float2 f0 = __half22float2(*(__half2*)&v.x);
        float2 f1 = __half22float2(*(__half2*)&v.y);
        float2 f2 = __half22float2(*(__half2*)&v.z);
        float2 f3 = __half22float2(*(__half2*)&v.w);
        a0.x += p.x * f0.x; a0.y += p.x * f0.y;
        a1.x += p.x * f1.x; a1.y += p.x * f1.y;
        a2.x += p.x * f2.x; a2.y += p.x * f2.y;
        a3.x += p.x * f3.x; a3.y += p.x * f3.y;
    }
    float r[8];
    if (subh) {
        uint4 sv = ((const uint4*)subh)[node * 8 + l];
        float2 s0 = __half22float2(*(__half2*)&sv.x);
        float2 s1 = __half22float2(*(__half2*)&sv.y);
        float2 s2 = __half22float2(*(__half2*)&sv.z);
        float2 s3 = __half22float2(*(__half2*)&sv.w);
        r[0] = alpha * a0.x + beta * s0.x; r[1] = alpha * a0.y + beta * s0.y;
        r[2] = alpha * a1.x + beta * s1.x; r[3] = alpha * a1.y + beta * s1.y;
        r[4] = alpha * a2.x + beta * s2.x; r[5] = alpha * a2.y + beta * s2.y;
        r[6] = alpha * a3.x + beta * s3.x; r[7] = alpha * a3.y + beta * s3.y;
    } else {
        r[0] = alpha * a0.x; r[1] = alpha * a0.y;
        r[2] = alpha * a1.x; r[3] = alpha * a1.y;
        r[4] = alpha * a2.x; r[5] = alpha * a2.y;
        r[6] = alpha * a3.x; r[7] = alpha * a3.y;
    }
    uint4 o;
    __half2 h0 = __floats2half2_rn(r[0], r[1]);
    __half2 h1 = __floats2half2_rn(r[2], r[3]);
    __half2 h2 = __floats2half2_rn(r[4], r[5]);
    __half2 h3 = __floats2half2_rn(r[6], r[7]);
    o.x = *(uint32_t*)&h0; o.y = *(uint32_t*)&h1;
    o.z = *(uint32_t*)&h2; o.w = *(uint32_t*)&h3;
    ((uint4*)outh)[node * 8 + l] = o;
}

// ---------------- fused layer GEMM -----------------------------------------
// out = relu([T0|T1|T2|T3] @ Wk + bk) + T0 @ Ws + bs ; also fp16 copy -> g_Hh
#define SMEM_LAYER (28928 * 4)
__global__ void __launch_bounds__(256, 2) k_layer(
        const float* __restrict__ T0,
        const float* __restrict__ Wk, const float* __restrict__ bk,
        const float* __restrict__ Ws, const float* __restrict__ bs,
        float* __restrict__ outp) {
    extern __shared__ float sm[];
    float* Wk_s = sm;            // 16384
    float* Ws_s = sm + 16384;    // 4096
    float* ins  = sm + 20480;    // 8192  [32 rows][256]
    float* bk_s = sm + 28672;    // 64
    float* bs_s = sm + 28736;    // 64
    const int t = threadIdx.x;   // 256 threads

    for (int j = t; j < 4096; j += 256) ((float4*)Wk_s)[j] = ((const float4*)Wk)[j];
    for (int j = t; j < 1024; j += 256) ((float4*)Ws_s)[j] = ((const float4*)Ws)[j];
    if (t < 64) { bk_s[t] = bk[t]; bs_s[t] = bs[t]; }

    const int cg = (t & 15) * 4;   // output col base (4 cols)
    const int r0 = (t >> 4) * 2;   // row base (2 rows)

    for (int tile = blockIdx.x; tile < NTILES; tile += gridDim.x) {
        const int rowbase = tile * 32;
        __syncthreads();
        {
            const float4* s0 = (const float4*)T0;
            const uint2* h1 = (const uint2*)g_T1h;
            const uint2* h2 = (const uint2*)g_T2h;
            const uint2* h3 = (const uint2*)g_T3h;
            #pragma unroll
            for (int j = 0; j < 2; j++) {
                int i = t + j * 256;
                int r = i >> 4, f4 = i & 15;
                int gidx = (rowbase + r) * 16 + f4;
                *(float4*)&ins[r * 256 + 0 + f4 * 4] = s0[gidx];
                uint2 u1 = h1[gidx], u2 = h2[gidx], u3 = h3[gidx];
                float2 a, b;
                a = __half22float2(*(__half2*)&u1.x);
                b = __half22float2(*(__half2*)&u1.y);
                *(float4*)&ins[r * 256 +  64 + f4 * 4] = make_float4(a.x, a.y, b.x, b.y);
                a = __half22float2(*(__half2*)&u2.x);
                b = __half22float2(*(__half2*)&u2.y);
                *(float4*)&ins[r * 256 + 128 + f4 * 4] = make_float4(a.x, a.y, b.x, b.y);
                a = __half22float2(*(__half2*)&u3.x);
                b = __half22float2(*(__half2*)&u3.y);
                *(float4*)&ins[r * 256 + 192 + f4 * 4] = make_float4(a.x, a.y, b.x, b.y);
            }
        }
        __syncthreads();

        const float* in0 = &ins[r0 * 256];
        const float* in1 = in0 + 256;
        float4 acc0 = make_float4(0, 0, 0, 0), acc1 = acc0;
        #pragma unroll 8
        for (int kk = 0; kk < 256; kk++) {
            float4 wv = *(const float4*)&Wk_s[kk * 64 + cg];
            float a0 = in0[kk], a1 = in1[kk];
            acc0.x += a0 * wv.x; acc0.y += a0 * wv.y; acc0.z += a0 * wv.z; acc0.w += a0 * wv.w;
            acc1.x += a1 * wv.x; acc1.y += a1 * wv.y; acc1.z += a1 * wv.z; acc1.w += a1 * wv.w;
        }
        float4 sk0 = make_float4(0, 0, 0, 0), sk1 = sk0;
        #pragma unroll 8
        for (int kk = 0; kk < 64; kk++) {
            float4 wv = *(const float4*)&Ws_s[kk * 64 + cg];
            float a0 = in0[kk], a1 = in1[kk];
            sk0.x += a0 * wv.x; sk0.y += a0 * wv.y; sk0.z += a0 * wv.z; sk0.w += a0 * wv.w;
            sk1.x += a1 * wv.x; sk1.y += a1 * wv.y; sk1.z += a1 * wv.z; sk1.w += a1 * wv.w;
        }
        float4 bkv = *(const float4*)&bk_s[cg];
        float4 bsv = *(const float4*)&bs_s[cg];
        float4 o0, o1;
        o0.x = fmaxf(acc0.x + bkv.x, 0.f) + sk0.x + bsv.x;
        o0.y = fmaxf(acc0.y + bkv.y, 0.f) + sk0.y + bsv.y;
        o0.z = fmaxf(acc0.z + bkv.z, 0.f) + sk0.z + bsv.z;
        o0.w = fmaxf(acc0.w + bkv.w, 0.f) + sk0.w + bsv.w;
        o1.x = fmaxf(acc1.x + bkv.x, 0.f) + sk1.x + bsv.x;
        o1.y = fmaxf(acc1.y + bkv.y, 0.f) + sk1.y + bsv.y;
        o1.z = fmaxf(acc1.z + bkv.z, 0.f) + sk1.z + bsv.z;
        o1.w = fmaxf(acc1.w + bkv.w, 0.f) + sk1.w + bsv.w;
        const int ro0 = rowbase + r0, ro1 = ro0 + 1;
        *(float4*)&outp[ro0 * 64 + cg] = o0;
        *(float4*)&outp[ro1 * 64 + cg] = o1;
        uint2 u;
        __half2 hh0 = __floats2half2_rn(o0.x, o0.y);
        __half2 hh1 = __floats2half2_rn(o0.z, o0.w);
        u.x = *(uint32_t*)&hh0; u.y = *(uint32_t*)&hh1;
        ((uint2*)g_Hh)[ro0 * 16 + (cg >> 2)] = u;
        hh0 = __floats2half2_rn(o1.x, o1.y);
        hh1 = __floats2half2_rn(o1.z, o1.w);
        u.x = *(uint32_t*)&hh0; u.y = *(uint32_t*)&hh1;
        ((uint2*)g_Hh)[ro1 * 16 + (cg >> 2)] = u;
    }
}

// ---------------- mix head GEMM: A = hc@W1, B = hc@W0 + b ------------------
#define SMEM_MIX (12320 * 4)
__global__ void __launch_bounds__(256, 4) k_mixgemm(
        const float* __restrict__ H, const float* __restrict__ x,
        const float* __restrict__ mw, const float* __restrict__ mb) {
    extern __shared__ float sm[];
    float* Wm_s = sm;           // 8192  [128][64]: cols 0..31 = W1, 32..63 = W0
    float* ins  = sm + 8192;    // 4096  [32 rows][128]
    float* mb_s = sm + 12288;   // 32
    const int t = threadIdx.x;

    for (int j = t; j < 8192; j += 256) {
        int f = j >> 6, col = j & 63;
        Wm_s[j] = (col < 32) ? mw[128 * 32 + f * 32 + col] : mw[f * 32 + (col - 32)];
    }
    if (t < 32) mb_s[t] = mb[t];

    const int cg = (t & 15) * 4;
    const int r0 = (t >> 4) * 2;

    for (int tile = blockIdx.x; tile < NTILES; tile += gridDim.x) {
        const int rowbase = tile * 32;
        __syncthreads();
        {
            const float4* sH = (const float4*)H;
            const float4* sx = (const float4*)x;
            #pragma unroll
            for (int j = 0; j < 2; j++) {
                int i = t + j * 256;
                int r = i >> 4, f4 = i & 15;
                int gidx = (rowbase + r) * 16 + f4;
                *(float4*)&ins[r * 128 +      f4 * 4] = sH[gidx];
                *(float4*)&ins[r * 128 + 64 + f4 * 4] = sx[gidx];
            }
        }
        __syncthreads();

        const float* in0 = &ins[r0 * 128];
        const float* in1 = in0 + 128;
        float4 acc0 = make_float4(0, 0, 0, 0), acc1 = acc0;
        #pragma unroll 8
        for (int kk = 0; kk < 128; kk++) {
            float4 wv = *(const float4*)&Wm_s[kk * 64 + cg];
            float a0 = in0[kk], a1 = in1[kk];
            acc0.x += a0 * wv.x; acc0.y += a0 * wv.y; acc0.z += a0 * wv.z; acc0.w += a0 * wv.w;
            acc1.x += a1 * wv.x; acc1.y += a1 * wv.y; acc1.z += a1 * wv.z; acc1.w += a1 * wv.w;
        }
        if (cg < 32) {
            *(float4*)&g_A[(rowbase + r0) * 32 + cg]     = acc0;
            *(float4*)&g_A[(rowbase + r0 + 1) * 32 + cg] = acc1;
        } else {
            float4 bv = *(const float4*)&mb_s[cg - 32];
            acc0.x += bv.x; acc0.y += bv.y; acc0.z += bv.z; acc0.w += bv.w;
            acc1.x += bv.x; acc1.y += bv.y; acc1.z += bv.z; acc1.w += bv.w;
            *(float4*)&g_B[(rowbase + r0) * 32 + cg - 32]     = acc0;
            *(float4*)&g_B[(rowbase + r0 + 1) * 32 + cg - 32] = acc1;
        }
    }
}

// ---- final: out = B + L(A), width 32; 4 nodes/warp, float4 gathers --------
__global__ void k_mixlmv(float* __restrict__ outp) {
    int gt = blockIdx.x * blockDim.x + threadIdx.x;
    int warp = gt >> 5;
    int node = warp * 4 + ((gt >> 3) & 3);   // NN % 4 == 0
    if (node >= NN) return;
    int l = gt & 7;                           // lane within quarter (0..7)
    int beg = g_rp[node], end = g_rp[node + 1];
    const float4* A4 = (const float4*)g_A;
    float4 acc = make_float4(0.f, 0.f, 0.f, 0.f);
    for (int e = beg; e < end; e++) {
        float2 p = g_wc[e];
        float4 v = A4[__float_as_int(p.y) * 8 + l];
        acc.x += p.x * v.x;
        acc.y += p.x * v.y;
        acc.z += p.x * v.z;
        acc.w += p.x * v.w;
    }
    float4 bv = ((const float4*)g_B)[node * 8 + l];
    float4 r = make_float4(bv.x + acc.x, bv.y + acc.y, bv.z + acc.z, bv.w + acc.w);
    ((float4*)outp)[node * 8 + l] = r;
}

// ---------------- launch ---------------------------------------------------
extern "C" void kernel_launch(void* const* d_in, const int* in_sizes, int n_in,
                              void* d_out, int out_size) {
    const float* x  = (const float*)d_in[0];
    const int*   ei = (const int*)d_in[1];
    const float* kw = (const float*)d_in[2];   // [3][4][64][64]
    const float* kb = (const float*)d_in[3];   // [3][64]
    const float* sw = (const float*)d_in[4];   // [3][64][64]
    const float* sb = (const float*)d_in[5];   // [3][64]
    const float* mw = (const float*)d_in[6];   // [2][128][32]
    const float* mb = (const float*)d_in[7];   // [32]
    float* outp = (float*)d_out;
    const int* src = ei;
    const int* dst = ei + NE;

    float *Ha, *Hb;
    __half2 *T1h, *T2h, *T3h, *Hh;
    cudaGetSymbolAddress((void**)&Ha, g_Ha);
    cudaGetSymbolAddress((void**)&Hb, g_Hb);
    cudaGetSymbolAddress((void**)&T1h, g_T1h);
    cudaGetSymbolAddress((void**)&T2h, g_T2h);
    cudaGetSymbolAddress((void**)&T3h, g_T3h);
    cudaGetSymbolAddress((void**)&Hh, g_Hh);

    cudaFuncSetAttribute(k_layer, cudaFuncAttributeMaxDynamicSharedMemorySize, SMEM_LAYER);
    cudaFuncSetAttribute(k_mixgemm, cudaFuncAttributeMaxDynamicSharedMemorySize, SMEM_MIX);

    const int gE = (NE + 255) / 256;            // 4688
    const int gN = NB;                          // 391
    const int gH = (NN * 16 + 255) / 256;       // 6250 (tohalf elements)
    const int gW = (NN / 4 * 32 + 255) / 256;   // 3125 (4 nodes per warp)
    const int gX = (NN / 4 * 32 + 255) / 256;   // 3125 (4 nodes per warp)
    const int gG = 296;                         // k_layer grid
    const int gM = 592;                         // mixgemm grid

    // graph setup: degrees, dinv, CSR by dst; fp16 copy of x
    k_zero3<<<gN, 256>>>();
    k_degcnt<<<gE, 256>>>(src, dst);
    k_dinv<<<gN, 256>>>();
    k_scan1<<<gN, 256>>>();
    k_scan2<<<1, 512>>>();
    k_scan3<<<gN, 256>>>();
    k_scatter<<<gE, 256>>>(src, dst);
    k_tohalf<<<gH, 256>>>(x);

    // layer 0: input = x (fp16 copy in g_Hh), output = Hb (+g_Hh)
    k_lmvh<<<gW, 256>>>(Hh, nullptr, T1h, 1.f, 0.f);
    k_lmvh<<<gW, 256>>>(T1h, Hh, T2h, 2.f, -1.f);
    k_lmvh<<<gW, 256>>>(T2h, T1h, T3h, 2.f, -1.f);
    k_layer<<<gG, 256, SMEM_LAYER>>>(x, kw, kb, sw, sb, Hb);

    // layer 1: Hb -> Ha
    k_lmvh<<<gW, 256>>>(Hh, nullptr, T1h, 1.f, 0.f);
    k_lmvh<<<gW, 256>>>(T1h, Hh, T2h, 2.f, -1.f);
    k_lmvh<<<gW, 256>>>(T2h, T1h, T3h, 2.f, -1.f);
    k_layer<<<gG, 256, SMEM_LAYER>>>(Hb, kw + 4 * 64 * 64, kb + 64, sw + 64 * 64, sb + 64, Ha);

    // layer 2: Ha -> Hb
    k_lmvh<<<gW, 256>>>(Hh, nullptr, T1h, 1.f, 0.f);
    k_lmvh<<<gW, 256>>>(T1h, Hh, T2h, 2.f, -1.f);
    k_lmvh<<<gW, 256>>>(T2h, T1h, T3h, 2.f, -1.f);
    k_layer<<<gG, 256, SMEM_LAYER>>>(Ha, kw + 8 * 64 * 64, kb + 128, sw + 2 * 64 * 64, sb + 128, Hb);

    // mix head: A = [Hb|x]@W1, B = [Hb|x]@W0 + b; out = B + L(A)
    k_mixgemm<<<gM, 256, SMEM_MIX>>>(Hb, x, mw, mb);
    k_mixlmv<<<gX, 256>>>(outp);
}